// round 1
// baseline (speedup 1.0000x reference)
#include <cuda_runtime.h>
#include <cuda_bf16.h>
#include <math.h>
#include <stdint.h>

#define N_NODES 131072
#define N_EDGES 524288
#define N_GRAPHS 4096
#define D 256
#define EPS 1e-10f

// ---------------- scratch (device globals; no allocation allowed) ----------
__device__ float g_hx0[N_NODES * D];
__device__ float g_hx1[N_NODES * D];          // aliases x
__device__ float g_e[N_EDGES * D];
__device__ float g_agg[N_NODES * D];          // x + sum(msg) -> GIN input
__device__ float g_t[N_NODES * 2 * D];        // GIN hidden
__device__ float g_xconv[N_NODES * D];
__device__ float g_gi[N_NODES * 3 * D];
__device__ float g_gh[N_NODES * 3 * D];
__device__ float g_g1[N_GRAPHS * 4 * D];
__device__ float g_g2[N_GRAPHS * 4 * D];
__device__ float g_hs[N_GRAPHS * D];
__device__ float g_cs[N_GRAPHS * D];
__device__ float g_qstar[N_GRAPHS * 2 * D];
__device__ float g_prod[N_NODES];
__device__ float g_m[N_GRAPHS];
__device__ float g_norm[N_GRAPHS];

// ---------------- helpers ----------------
__device__ __forceinline__ void atomicMaxFloat(float* addr, float val) {
    int* ia = (int*)addr;
    int cur = __float_as_int(*(volatile float*)addr);
    while (__int_as_float(cur) < val) {
        int old = atomicCAS(ia, cur, __float_as_int(val));
        if (old == cur) break;
        cur = old;
    }
}

__device__ __forceinline__ float sigmoidf_(float x) { return 1.0f / (1.0f + expf(-x)); }

// ---------------- encoders ----------------
__global__ void atom_encode_kernel(const int* __restrict__ xa,
                                   const float* __restrict__ emb,
                                   float* __restrict__ hx0, float* __restrict__ hx1) {
    size_t idx = (size_t)blockIdx.x * blockDim.x + threadIdx.x;
    if (idx >= (size_t)N_NODES * 64) return;
    int n = (int)(idx >> 6);
    int c = (int)(idx & 63);
    float4 acc = make_float4(0.f, 0.f, 0.f, 0.f);
#pragma unroll
    for (int i = 0; i < 9; i++) {
        int t = xa[n * 9 + i];
        const float4 v = *(const float4*)&emb[((size_t)(i * 120 + t)) * D + c * 4];
        acc.x += v.x; acc.y += v.y; acc.z += v.z; acc.w += v.w;
    }
    *(float4*)&hx0[(size_t)n * D + c * 4] = acc;
    *(float4*)&hx1[(size_t)n * D + c * 4] = acc;
}

__global__ void bond_encode_kernel(const int* __restrict__ ea,
                                   const float* __restrict__ emb,
                                   float* __restrict__ e_out) {
    size_t idx = (size_t)blockIdx.x * blockDim.x + threadIdx.x;
    if (idx >= (size_t)N_EDGES * 64) return;
    int n = (int)(idx >> 6);
    int c = (int)(idx & 63);
    float4 acc = make_float4(0.f, 0.f, 0.f, 0.f);
#pragma unroll
    for (int i = 0; i < 3; i++) {
        int t = ea[n * 3 + i];
        const float4 v = *(const float4*)&emb[((size_t)(i * 6 + t)) * D + c * 4];
        acc.x += v.x; acc.y += v.y; acc.z += v.z; acc.w += v.w;
    }
    *(float4*)&e_out[(size_t)n * D + c * 4] = acc;
}

// ---------------- elementwise ----------------
__global__ void copy4_kernel(float* __restrict__ dst, const float* __restrict__ src, size_t n4) {
    size_t i = (size_t)blockIdx.x * blockDim.x + threadIdx.x;
    if (i < n4) ((float4*)dst)[i] = ((const float4*)src)[i];
}

// msg = relu(x[src] + e), agg[dst] += msg (agg preloaded with x)
__global__ void edge_scatter_kernel(const int* __restrict__ ei,
                                    const float* __restrict__ x,
                                    const float* __restrict__ e,
                                    float* __restrict__ agg) {
    size_t idx = (size_t)blockIdx.x * blockDim.x + threadIdx.x;
    if (idx >= (size_t)N_EDGES * 64) return;
    int ed = (int)(idx >> 6);
    int c = (int)(idx & 63);
    int s = ei[ed];
    int d = ei[N_EDGES + ed];
    float4 xv = *(const float4*)&x[(size_t)s * D + c * 4];
    float4 ev = *(const float4*)&e[(size_t)ed * D + c * 4];
    float4 m;
    m.x = fmaxf(xv.x + ev.x, 0.f);
    m.y = fmaxf(xv.y + ev.y, 0.f);
    m.z = fmaxf(xv.z + ev.z, 0.f);
    m.w = fmaxf(xv.w + ev.w, 0.f);
    atomicAdd((float4*)&agg[(size_t)d * D + c * 4], m);
}

// ---------------- SGEMM: C[M,N] = A[M,K] @ op(B) + bias (optional relu) ----
// BT=false: B is [K,N] row-major. BT=true: B is [N,K] row-major (C = A @ B^T).
// Requires M%128==0, N%128==0, K%16==0.
template <bool BT, bool RELU>
__global__ __launch_bounds__(256, 2) void sgemm_kernel(
    const float* __restrict__ A, const float* __restrict__ B,
    const float* __restrict__ bias, float* __restrict__ C,
    int M, int N, int K) {
    constexpr int BM = 128, BN = 128, BK = 16, TM = 8, TN = 8;
    __shared__ float As[BK][BM + 4];
    __shared__ float Bs[BK][BN + 4];
    const int tid = threadIdx.x;
    const int m0 = blockIdx.y * BM;
    const int n0 = blockIdx.x * BN;
    const int tx = tid & 15;
    const int ty = tid >> 4;
    float acc[TM][TN] = {};

    for (int k0 = 0; k0 < K; k0 += BK) {
#pragma unroll
        for (int i = 0; i < 2; i++) {
            int v = tid + i * 256;              // 0..511 float4s
            int row = v >> 2;                   // 0..127
            int c4 = v & 3;                     // 0..3
            float4 a = *(const float4*)&A[(size_t)(m0 + row) * K + k0 + c4 * 4];
            As[c4 * 4 + 0][row] = a.x;
            As[c4 * 4 + 1][row] = a.y;
            As[c4 * 4 + 2][row] = a.z;
            As[c4 * 4 + 3][row] = a.w;
        }
        if (BT) {
#pragma unroll
            for (int i = 0; i < 2; i++) {
                int v = tid + i * 256;
                int row = v >> 2;               // n index 0..127
                int c4 = v & 3;
                float4 b = *(const float4*)&B[(size_t)(n0 + row) * K + k0 + c4 * 4];
                Bs[c4 * 4 + 0][row] = b.x;
                Bs[c4 * 4 + 1][row] = b.y;
                Bs[c4 * 4 + 2][row] = b.z;
                Bs[c4 * 4 + 3][row] = b.w;
            }
        } else {
#pragma unroll
            for (int i = 0; i < 2; i++) {
                int v = tid + i * 256;
                int row = v >> 5;               // k index 0..15
                int c4 = v & 31;                // 0..31
                float4 b = *(const float4*)&B[(size_t)(k0 + row) * N + n0 + c4 * 4];
                Bs[row][c4 * 4 + 0] = b.x;
                Bs[row][c4 * 4 + 1] = b.y;
                Bs[row][c4 * 4 + 2] = b.z;
                Bs[row][c4 * 4 + 3] = b.w;
            }
        }
        __syncthreads();
#pragma unroll
        for (int kk = 0; kk < BK; kk++) {
            float4 a0 = *(const float4*)&As[kk][ty * TM];
            float4 a1 = *(const float4*)&As[kk][ty * TM + 4];
            float4 b0 = *(const float4*)&Bs[kk][tx * TN];
            float4 b1 = *(const float4*)&Bs[kk][tx * TN + 4];
            float ar[TM] = {a0.x, a0.y, a0.z, a0.w, a1.x, a1.y, a1.z, a1.w};
            float br[TN] = {b0.x, b0.y, b0.z, b0.w, b1.x, b1.y, b1.z, b1.w};
#pragma unroll
            for (int i = 0; i < TM; i++)
#pragma unroll
                for (int j = 0; j < TN; j++) acc[i][j] += ar[i] * br[j];
        }
        __syncthreads();
    }
#pragma unroll
    for (int i = 0; i < TM; i++) {
        int m = m0 + ty * TM + i;
#pragma unroll
        for (int j = 0; j < TN; j++) {
            int n = n0 + tx * TN + j;
            float v = acc[i][j];
            if (bias) v += bias[n];
            if (RELU) v = fmaxf(v, 0.f);
            C[(size_t)m * N + n] = v;
        }
    }
}

// ---------------- GRU / LSTM gates ----------------
__global__ void gru_gate_kernel(const float* __restrict__ gi,
                                const float* __restrict__ gh,
                                float* __restrict__ hx) {
    size_t idx = (size_t)blockIdx.x * blockDim.x + threadIdx.x;
    if (idx >= (size_t)N_NODES * D) return;
    int n = (int)(idx >> 8);
    int d = (int)(idx & 255);
    size_t base = (size_t)n * 3 * D + d;
    float ir = gi[base], iz = gi[base + D], in_ = gi[base + 2 * D];
    float hr = gh[base], hz = gh[base + D], hn = gh[base + 2 * D];
    float r = sigmoidf_(ir + hr);
    float z = sigmoidf_(iz + hz);
    float nn = tanhf(in_ + r * hn);
    float hprev = hx[idx];
    hx[idx] = (1.0f - z) * nn + z * hprev;
}

__global__ void lstm_gate_kernel(const float* __restrict__ g1,
                                 const float* __restrict__ g2,
                                 float* __restrict__ hs, float* __restrict__ cs) {
    size_t idx = (size_t)blockIdx.x * blockDim.x + threadIdx.x;
    if (idx >= (size_t)N_GRAPHS * D) return;
    int b = (int)(idx >> 8);
    int d = (int)(idx & 255);
    size_t base = (size_t)b * 4 * D + d;
    float ig = sigmoidf_(g1[base] + g2[base]);
    float fg = sigmoidf_(g1[base + D] + g2[base + D]);
    float gg = tanhf(g1[base + 2 * D] + g2[base + 2 * D]);
    float og = sigmoidf_(g1[base + 3 * D] + g2[base + 3 * D]);
    float c = fg * cs[idx] + ig * gg;
    cs[idx] = c;
    hs[idx] = og * tanhf(c);
}

// ---------------- Set2Set attention ----------------
__global__ void s2s_prep_kernel(float* __restrict__ qstar,
                                const float* __restrict__ hs,
                                float* __restrict__ m, float* __restrict__ norm) {
    size_t i = (size_t)blockIdx.x * blockDim.x + threadIdx.x;
    if (i < N_GRAPHS) { m[i] = -INFINITY; norm[i] = 0.f; }
    if (i < (size_t)N_GRAPHS * D) {
        int b = (int)(i >> 8);
        int d = (int)(i & 255);
        qstar[(size_t)b * 2 * D + d] = hs[i];
        qstar[(size_t)b * 2 * D + D + d] = 0.f;
    }
}

__global__ void attn_prod_kernel(const float* __restrict__ hs,
                                 const float* __restrict__ x,
                                 const int* __restrict__ batch,
                                 float* __restrict__ prod) {
    int warp = (int)(((size_t)blockIdx.x * blockDim.x + threadIdx.x) >> 5);
    int lane = threadIdx.x & 31;
    if (warp >= N_NODES) return;
    int b = batch[warp];
    const float* q = hs + (size_t)b * D;
    const float* xv = x + (size_t)warp * D;
    float s = 0.f;
#pragma unroll
    for (int j = 0; j < D / 32; j++) s += q[lane + j * 32] * xv[lane + j * 32];
#pragma unroll
    for (int o = 16; o; o >>= 1) s += __shfl_xor_sync(0xFFFFFFFFu, s, o);
    if (lane == 0) prod[warp] = s;
}

__global__ void attn_max_kernel(const int* __restrict__ batch,
                                const float* __restrict__ prod,
                                float* __restrict__ m) {
    int n = (int)((size_t)blockIdx.x * blockDim.x + threadIdx.x);
    if (n >= N_NODES) return;
    atomicMaxFloat(&m[batch[n]], prod[n]);
}

__global__ void attn_expnorm_kernel(const int* __restrict__ batch,
                                    float* __restrict__ prod,
                                    const float* __restrict__ m,
                                    float* __restrict__ norm) {
    int n = (int)((size_t)blockIdx.x * blockDim.x + threadIdx.x);
    if (n >= N_NODES) return;
    int b = batch[n];
    float a = expf(prod[n] - m[b]);
    prod[n] = a;
    atomicAdd(&norm[b], a);
}

__global__ void attn_scatter_kernel(const int* __restrict__ batch,
                                    const float* __restrict__ prod,
                                    const float* __restrict__ norm,
                                    const float* __restrict__ x,
                                    float* __restrict__ qstar) {
    size_t idx = (size_t)blockIdx.x * blockDim.x + threadIdx.x;
    if (idx >= (size_t)N_NODES * 64) return;
    int n = (int)(idx >> 6);
    int c = (int)(idx & 63);
    int b = batch[n];
    float coef = prod[n] / (norm[b] + EPS);
    float4 xv = *(const float4*)&x[(size_t)n * D + c * 4];
    float4 v = make_float4(coef * xv.x, coef * xv.y, coef * xv.z, coef * xv.w);
    atomicAdd((float4*)&qstar[(size_t)b * 2 * D + D + c * 4], v);
}

__global__ void fc_kernel(const float* __restrict__ qstar,
                          const float* __restrict__ fw,
                          const float* __restrict__ fb,
                          float* __restrict__ out) {
    int warp = (int)(((size_t)blockIdx.x * blockDim.x + threadIdx.x) >> 5);
    int lane = threadIdx.x & 31;
    if (warp >= N_GRAPHS) return;
    float s = 0.f;
#pragma unroll
    for (int j = 0; j < (2 * D) / 32; j++)
        s += qstar[(size_t)warp * 2 * D + lane + j * 32] * fw[lane + j * 32];
#pragma unroll
    for (int o = 16; o; o >>= 1) s += __shfl_xor_sync(0xFFFFFFFFu, s, o);
    if (lane == 0) out[warp] = s + fb[0];
}

// ---------------- launch ----------------
extern "C" void kernel_launch(void* const* d_in, const int* in_sizes, int n_in,
                              void* d_out, int out_size) {
    const int* x_atoms = (const int*)d_in[0];
    const int* edge_index = (const int*)d_in[1];
    const int* edge_attr = (const int*)d_in[2];
    const int* batch = (const int*)d_in[3];
    const float* atom_emb = (const float*)d_in[4];
    const float* bond_emb = (const float*)d_in[5];
    const float* gin_w1 = (const float*)d_in[6];
    const float* gin_b1 = (const float*)d_in[7];
    const float* gin_w2 = (const float*)d_in[8];
    const float* gin_b2 = (const float*)d_in[9];
    const float* gru_wih = (const float*)d_in[10];
    const float* gru_whh = (const float*)d_in[11];
    const float* gru_bih = (const float*)d_in[12];
    const float* gru_bhh = (const float*)d_in[13];
    const float* lstm_wih = (const float*)d_in[14];
    const float* lstm_whh = (const float*)d_in[15];
    const float* lstm_bih = (const float*)d_in[16];
    const float* lstm_bhh = (const float*)d_in[17];
    const float* fc_w = (const float*)d_in[18];
    const float* fc_b = (const float*)d_in[19];
    float* out = (float*)d_out;

    float *hx0, *hx1, *e, *agg, *t, *xconv, *gi, *gh, *g1, *g2, *hs, *cs, *qstar, *prod, *mbuf, *norm;
    cudaGetSymbolAddress((void**)&hx0, g_hx0);
    cudaGetSymbolAddress((void**)&hx1, g_hx1);
    cudaGetSymbolAddress((void**)&e, g_e);
    cudaGetSymbolAddress((void**)&agg, g_agg);
    cudaGetSymbolAddress((void**)&t, g_t);
    cudaGetSymbolAddress((void**)&xconv, g_xconv);
    cudaGetSymbolAddress((void**)&gi, g_gi);
    cudaGetSymbolAddress((void**)&gh, g_gh);
    cudaGetSymbolAddress((void**)&g1, g_g1);
    cudaGetSymbolAddress((void**)&g2, g_g2);
    cudaGetSymbolAddress((void**)&hs, g_hs);
    cudaGetSymbolAddress((void**)&cs, g_cs);
    cudaGetSymbolAddress((void**)&qstar, g_qstar);
    cudaGetSymbolAddress((void**)&prod, g_prod);
    cudaGetSymbolAddress((void**)&mbuf, g_m);
    cudaGetSymbolAddress((void**)&norm, g_norm);

    const int TPB = 256;

    // encoders + S2S state init
    atom_encode_kernel<<<(N_NODES * 64) / TPB, TPB>>>(x_atoms, atom_emb, hx0, hx1);
    bond_encode_kernel<<<(N_EDGES * 64) / TPB, TPB>>>(edge_attr, bond_emb, e);
    cudaMemsetAsync(hs, 0, (size_t)N_GRAPHS * D * sizeof(float));
    cudaMemsetAsync(cs, 0, (size_t)N_GRAPHS * D * sizeof(float));
    cudaMemsetAsync(qstar, 0, (size_t)N_GRAPHS * 2 * D * sizeof(float));

    for (int layer = 0; layer < 3; layer++) {
        // agg = x, then agg[dst] += relu(x[src] + e)
        copy4_kernel<<<(N_NODES * D / 4) / TPB, TPB>>>(agg, hx1, (size_t)N_NODES * D / 4);
        edge_scatter_kernel<<<(N_EDGES * 64) / TPB, TPB>>>(edge_index, hx1, e, agg);
        // GIN MLP
        sgemm_kernel<false, true><<<dim3(512 / 128, N_NODES / 128), TPB>>>(
            agg, gin_w1, gin_b1, t, N_NODES, 512, 256);
        sgemm_kernel<false, false><<<dim3(256 / 128, N_NODES / 128), TPB>>>(
            t, gin_w2, gin_b2, xconv, N_NODES, 256, 512);
        // GRU layer 0
        sgemm_kernel<true, false><<<dim3(768 / 128, N_NODES / 128), TPB>>>(
            xconv, gru_wih, gru_bih, gi, N_NODES, 768, 256);
        sgemm_kernel<true, false><<<dim3(768 / 128, N_NODES / 128), TPB>>>(
            hx0, gru_whh, gru_bhh, gh, N_NODES, 768, 256);
        gru_gate_kernel<<<(N_NODES * D) / TPB, TPB>>>(gi, gh, hx0);
        // GRU layer 1
        sgemm_kernel<true, false><<<dim3(768 / 128, N_NODES / 128), TPB>>>(
            hx0, gru_wih + 768 * 256, gru_bih + 768, gi, N_NODES, 768, 256);
        sgemm_kernel<true, false><<<dim3(768 / 128, N_NODES / 128), TPB>>>(
            hx1, gru_whh + 768 * 256, gru_bhh + 768, gh, N_NODES, 768, 256);
        gru_gate_kernel<<<(N_NODES * D) / TPB, TPB>>>(gi, gh, hx1);
    }

    // Set2Set
    for (int step = 0; step < 3; step++) {
        sgemm_kernel<true, false><<<dim3(1024 / 128, N_GRAPHS / 128), TPB>>>(
            qstar, lstm_wih, lstm_bih, g1, N_GRAPHS, 1024, 512);
        sgemm_kernel<true, false><<<dim3(1024 / 128, N_GRAPHS / 128), TPB>>>(
            hs, lstm_whh, lstm_bhh, g2, N_GRAPHS, 1024, 256);
        lstm_gate_kernel<<<(N_GRAPHS * D) / TPB, TPB>>>(g1, g2, hs, cs);
        s2s_prep_kernel<<<(N_GRAPHS * D) / TPB, TPB>>>(qstar, hs, mbuf, norm);
        attn_prod_kernel<<<(N_NODES * 32) / TPB, TPB>>>(hs, hx1, batch, prod);
        attn_max_kernel<<<N_NODES / TPB, TPB>>>(batch, prod, mbuf);
        attn_expnorm_kernel<<<N_NODES / TPB, TPB>>>(batch, prod, mbuf, norm);
        attn_scatter_kernel<<<(N_NODES * 64) / TPB, TPB>>>(batch, prod, norm, hx1, qstar);
    }

    fc_kernel<<<(N_GRAPHS * 32) / TPB, TPB>>>(qstar, fc_w, fc_b, out);
}

// round 2
// speedup vs baseline: 1.9451x; 1.9451x over previous
#include <cuda_runtime.h>
#include <cuda_bf16.h>
#include <math.h>
#include <stdint.h>

#define N_NODES 131072
#define N_EDGES 524288
#define N_GRAPHS 4096
#define D 256
#define EPS 1e-10f

// ---------------- scratch (device globals; no allocation allowed) ----------
__device__ float g_hx0[N_NODES * D];
__device__ float g_hx1[N_NODES * D];          // aliases x
__device__ float g_e[N_EDGES * D];
__device__ float g_agg[N_NODES * D];          // x + sum(msg) -> GIN input
__device__ float g_t[N_NODES * 2 * D];        // GIN hidden
__device__ float g_xconv[N_NODES * D];
__device__ float g_gi[N_NODES * 3 * D];
__device__ float g_gh[N_NODES * 3 * D];
__device__ float g_g1[N_GRAPHS * 4 * D];
__device__ float g_g2[N_GRAPHS * 4 * D];
__device__ float g_hs[N_GRAPHS * D];
__device__ float g_cs[N_GRAPHS * D];
__device__ float g_qstar[N_GRAPHS * 2 * D];
__device__ float g_prod[N_NODES];
__device__ float g_m[N_GRAPHS];
__device__ float g_norm[N_GRAPHS];

// ---------------- helpers ----------------
__device__ __forceinline__ void atomicMaxFloat(float* addr, float val) {
    int* ia = (int*)addr;
    int cur = __float_as_int(*(volatile float*)addr);
    while (__int_as_float(cur) < val) {
        int old = atomicCAS(ia, cur, __float_as_int(val));
        if (old == cur) break;
        cur = old;
    }
}

__device__ __forceinline__ float sigmoidf_(float x) { return 1.0f / (1.0f + expf(-x)); }

__device__ __forceinline__ uint32_t to_tf32(float x) {
    uint32_t u;
    asm("cvt.rna.tf32.f32 %0, %1;" : "=r"(u) : "f"(x));
    return u;
}

// ---------------- encoders ----------------
__global__ void atom_encode_kernel(const int* __restrict__ xa,
                                   const float* __restrict__ emb,
                                   float* __restrict__ hx0, float* __restrict__ hx1) {
    size_t idx = (size_t)blockIdx.x * blockDim.x + threadIdx.x;
    if (idx >= (size_t)N_NODES * 64) return;
    int n = (int)(idx >> 6);
    int c = (int)(idx & 63);
    float4 acc = make_float4(0.f, 0.f, 0.f, 0.f);
#pragma unroll
    for (int i = 0; i < 9; i++) {
        int t = xa[n * 9 + i];
        const float4 v = *(const float4*)&emb[((size_t)(i * 120 + t)) * D + c * 4];
        acc.x += v.x; acc.y += v.y; acc.z += v.z; acc.w += v.w;
    }
    *(float4*)&hx0[(size_t)n * D + c * 4] = acc;
    *(float4*)&hx1[(size_t)n * D + c * 4] = acc;
}

__global__ void bond_encode_kernel(const int* __restrict__ ea,
                                   const float* __restrict__ emb,
                                   float* __restrict__ e_out) {
    size_t idx = (size_t)blockIdx.x * blockDim.x + threadIdx.x;
    if (idx >= (size_t)N_EDGES * 64) return;
    int n = (int)(idx >> 6);
    int c = (int)(idx & 63);
    float4 acc = make_float4(0.f, 0.f, 0.f, 0.f);
#pragma unroll
    for (int i = 0; i < 3; i++) {
        int t = ea[n * 3 + i];
        const float4 v = *(const float4*)&emb[((size_t)(i * 6 + t)) * D + c * 4];
        acc.x += v.x; acc.y += v.y; acc.z += v.z; acc.w += v.w;
    }
    *(float4*)&e_out[(size_t)n * D + c * 4] = acc;
}

// ---------------- elementwise ----------------
__global__ void copy4_kernel(float* __restrict__ dst, const float* __restrict__ src, size_t n4) {
    size_t i = (size_t)blockIdx.x * blockDim.x + threadIdx.x;
    if (i < n4) ((float4*)dst)[i] = ((const float4*)src)[i];
}

// msg = relu(x[src] + e), agg[dst] += msg (agg preloaded with x)
__global__ void edge_scatter_kernel(const int* __restrict__ ei,
                                    const float* __restrict__ x,
                                    const float* __restrict__ e,
                                    float* __restrict__ agg) {
    size_t idx = (size_t)blockIdx.x * blockDim.x + threadIdx.x;
    if (idx >= (size_t)N_EDGES * 64) return;
    int ed = (int)(idx >> 6);
    int c = (int)(idx & 63);
    int s = ei[ed];
    int d = ei[N_EDGES + ed];
    float4 xv = *(const float4*)&x[(size_t)s * D + c * 4];
    float4 ev = *(const float4*)&e[(size_t)ed * D + c * 4];
    float4 m;
    m.x = fmaxf(xv.x + ev.x, 0.f);
    m.y = fmaxf(xv.y + ev.y, 0.f);
    m.z = fmaxf(xv.z + ev.z, 0.f);
    m.w = fmaxf(xv.w + ev.w, 0.f);
    atomicAdd((float4*)&agg[(size_t)d * D + c * 4], m);
}

// ---------------- tf32 tensor-core GEMM -----------------------------------
// C[M,N] = A[M,K] @ op(B) + bias (optional relu)
// BT=false: B is [K,N] row-major. BT=true: B is [N,K] row-major (C = A @ B^T).
// Requires M%128==0, N%128==0, K%32==0.
// Block 128x128, BK=32, 8 warps in 4(m) x 2(n), warp tile 32x64.
// mma.sync.aligned.m16n8k8 tf32, fp32 accumulate.
template <bool BT, bool RELU>
__global__ __launch_bounds__(256) void mma_gemm_kernel(
    const float* __restrict__ A, const float* __restrict__ B,
    const float* __restrict__ bias, float* __restrict__ C,
    int M, int N, int K) {
    constexpr int BM = 128, BN = 128, BK = 32;
    __shared__ uint32_t As[BK][BM + 4];
    __shared__ uint32_t Bs[BK][BN + 4];
    const int tid = threadIdx.x;
    const int lane = tid & 31;
    const int warp = tid >> 5;
    const int wm = warp & 3;          // 4 warps along M
    const int wn = warp >> 2;         // 2 warps along N
    const int m0 = blockIdx.y * BM;
    const int n0 = blockIdx.x * BN;

    float c[2][8][4];
#pragma unroll
    for (int i = 0; i < 2; i++)
#pragma unroll
        for (int j = 0; j < 8; j++)
#pragma unroll
            for (int r = 0; r < 4; r++) c[i][j][r] = 0.f;

    for (int k0 = 0; k0 < K; k0 += BK) {
        // stage A tile: 128 rows x 32 k = 1024 float4; 4 per thread
#pragma unroll
        for (int i = 0; i < 4; i++) {
            int v = tid + i * 256;
            int row = v >> 3;            // 0..127 (m)
            int c4 = v & 7;              // 0..7
            float4 a = *(const float4*)&A[(size_t)(m0 + row) * K + k0 + c4 * 4];
            As[c4 * 4 + 0][row] = to_tf32(a.x);
            As[c4 * 4 + 1][row] = to_tf32(a.y);
            As[c4 * 4 + 2][row] = to_tf32(a.z);
            As[c4 * 4 + 3][row] = to_tf32(a.w);
        }
        if (BT) {
#pragma unroll
            for (int i = 0; i < 4; i++) {
                int v = tid + i * 256;
                int row = v >> 3;        // 0..127 (n)
                int c4 = v & 7;
                float4 b = *(const float4*)&B[(size_t)(n0 + row) * K + k0 + c4 * 4];
                Bs[c4 * 4 + 0][row] = to_tf32(b.x);
                Bs[c4 * 4 + 1][row] = to_tf32(b.y);
                Bs[c4 * 4 + 2][row] = to_tf32(b.z);
                Bs[c4 * 4 + 3][row] = to_tf32(b.w);
            }
        } else {
#pragma unroll
            for (int i = 0; i < 4; i++) {
                int v = tid + i * 256;
                int krow = v >> 5;       // 0..31 (k)
                int c4 = v & 31;         // 0..31
                float4 b = *(const float4*)&B[(size_t)(k0 + krow) * N + n0 + c4 * 4];
                Bs[krow][c4 * 4 + 0] = to_tf32(b.x);
                Bs[krow][c4 * 4 + 1] = to_tf32(b.y);
                Bs[krow][c4 * 4 + 2] = to_tf32(b.z);
                Bs[krow][c4 * 4 + 3] = to_tf32(b.w);
            }
        }
        __syncthreads();

#pragma unroll
        for (int ks = 0; ks < 4; ks++) {
            int kb = ks * 8 + (lane & 3);
            uint32_t a[2][4];
#pragma unroll
            for (int i = 0; i < 2; i++) {
                int mr = wm * 32 + i * 16 + (lane >> 2);
                a[i][0] = As[kb][mr];
                a[i][1] = As[kb][mr + 8];
                a[i][2] = As[kb + 4][mr];
                a[i][3] = As[kb + 4][mr + 8];
            }
            uint32_t b[8][2];
#pragma unroll
            for (int j = 0; j < 8; j++) {
                int nc = wn * 64 + j * 8 + (lane >> 2);
                b[j][0] = Bs[kb][nc];
                b[j][1] = Bs[kb + 4][nc];
            }
#pragma unroll
            for (int i = 0; i < 2; i++)
#pragma unroll
                for (int j = 0; j < 8; j++) {
                    asm volatile(
                        "mma.sync.aligned.m16n8k8.row.col.f32.tf32.tf32.f32 "
                        "{%0,%1,%2,%3}, {%4,%5,%6,%7}, {%8,%9}, {%0,%1,%2,%3};"
                        : "+f"(c[i][j][0]), "+f"(c[i][j][1]),
                          "+f"(c[i][j][2]), "+f"(c[i][j][3])
                        : "r"(a[i][0]), "r"(a[i][1]), "r"(a[i][2]), "r"(a[i][3]),
                          "r"(b[j][0]), "r"(b[j][1]));
                }
        }
        __syncthreads();
    }

    // epilogue: c0,c1 -> (row, 2col); c2,c3 -> (row+8, 2col)
#pragma unroll
    for (int i = 0; i < 2; i++) {
        int mr = m0 + wm * 32 + i * 16 + (lane >> 2);
#pragma unroll
        for (int j = 0; j < 8; j++) {
            int nc = n0 + wn * 64 + j * 8 + (lane & 3) * 2;
            float b0 = bias ? bias[nc] : 0.f;
            float b1 = bias ? bias[nc + 1] : 0.f;
            float v0 = c[i][j][0] + b0;
            float v1 = c[i][j][1] + b1;
            float v2 = c[i][j][2] + b0;
            float v3 = c[i][j][3] + b1;
            if (RELU) {
                v0 = fmaxf(v0, 0.f); v1 = fmaxf(v1, 0.f);
                v2 = fmaxf(v2, 0.f); v3 = fmaxf(v3, 0.f);
            }
            *(float2*)&C[(size_t)mr * N + nc] = make_float2(v0, v1);
            *(float2*)&C[(size_t)(mr + 8) * N + nc] = make_float2(v2, v3);
        }
    }
}

// ---------------- GRU / LSTM gates ----------------
__global__ void gru_gate_kernel(const float* __restrict__ gi,
                                const float* __restrict__ gh,
                                float* __restrict__ hx) {
    size_t idx = (size_t)blockIdx.x * blockDim.x + threadIdx.x;
    if (idx >= (size_t)N_NODES * D) return;
    int n = (int)(idx >> 8);
    int d = (int)(idx & 255);
    size_t base = (size_t)n * 3 * D + d;
    float ir = gi[base], iz = gi[base + D], in_ = gi[base + 2 * D];
    float hr = gh[base], hz = gh[base + D], hn = gh[base + 2 * D];
    float r = sigmoidf_(ir + hr);
    float z = sigmoidf_(iz + hz);
    float nn = tanhf(in_ + r * hn);
    float hprev = hx[idx];
    hx[idx] = (1.0f - z) * nn + z * hprev;
}

__global__ void lstm_gate_kernel(const float* __restrict__ g1,
                                 const float* __restrict__ g2,
                                 float* __restrict__ hs, float* __restrict__ cs) {
    size_t idx = (size_t)blockIdx.x * blockDim.x + threadIdx.x;
    if (idx >= (size_t)N_GRAPHS * D) return;
    int b = (int)(idx >> 8);
    int d = (int)(idx & 255);
    size_t base = (size_t)b * 4 * D + d;
    float ig = sigmoidf_(g1[base] + g2[base]);
    float fg = sigmoidf_(g1[base + D] + g2[base + D]);
    float gg = tanhf(g1[base + 2 * D] + g2[base + 2 * D]);
    float og = sigmoidf_(g1[base + 3 * D] + g2[base + 3 * D]);
    float c = fg * cs[idx] + ig * gg;
    cs[idx] = c;
    hs[idx] = og * tanhf(c);
}

// ---------------- Set2Set attention ----------------
__global__ void s2s_prep_kernel(float* __restrict__ qstar,
                                const float* __restrict__ hs,
                                float* __restrict__ m, float* __restrict__ norm) {
    size_t i = (size_t)blockIdx.x * blockDim.x + threadIdx.x;
    if (i < N_GRAPHS) { m[i] = -INFINITY; norm[i] = 0.f; }
    if (i < (size_t)N_GRAPHS * D) {
        int b = (int)(i >> 8);
        int d = (int)(i & 255);
        qstar[(size_t)b * 2 * D + d] = hs[i];
        qstar[(size_t)b * 2 * D + D + d] = 0.f;
    }
}

__global__ void attn_prod_kernel(const float* __restrict__ hs,
                                 const float* __restrict__ x,
                                 const int* __restrict__ batch,
                                 float* __restrict__ prod) {
    int warp = (int)(((size_t)blockIdx.x * blockDim.x + threadIdx.x) >> 5);
    int lane = threadIdx.x & 31;
    if (warp >= N_NODES) return;
    int b = batch[warp];
    const float* q = hs + (size_t)b * D;
    const float* xv = x + (size_t)warp * D;
    float s = 0.f;
#pragma unroll
    for (int j = 0; j < D / 32; j++) s += q[lane + j * 32] * xv[lane + j * 32];
#pragma unroll
    for (int o = 16; o; o >>= 1) s += __shfl_xor_sync(0xFFFFFFFFu, s, o);
    if (lane == 0) prod[warp] = s;
}

__global__ void attn_max_kernel(const int* __restrict__ batch,
                                const float* __restrict__ prod,
                                float* __restrict__ m) {
    int n = (int)((size_t)blockIdx.x * blockDim.x + threadIdx.x);
    if (n >= N_NODES) return;
    atomicMaxFloat(&m[batch[n]], prod[n]);
}

__global__ void attn_expnorm_kernel(const int* __restrict__ batch,
                                    float* __restrict__ prod,
                                    const float* __restrict__ m,
                                    float* __restrict__ norm) {
    int n = (int)((size_t)blockIdx.x * blockDim.x + threadIdx.x);
    if (n >= N_NODES) return;
    int b = batch[n];
    float a = expf(prod[n] - m[b]);
    prod[n] = a;
    atomicAdd(&norm[b], a);
}

__global__ void attn_scatter_kernel(const int* __restrict__ batch,
                                    const float* __restrict__ prod,
                                    const float* __restrict__ norm,
                                    const float* __restrict__ x,
                                    float* __restrict__ qstar) {
    size_t idx = (size_t)blockIdx.x * blockDim.x + threadIdx.x;
    if (idx >= (size_t)N_NODES * 64) return;
    int n = (int)(idx >> 6);
    int c = (int)(idx & 63);
    int b = batch[n];
    float coef = prod[n] / (norm[b] + EPS);
    float4 xv = *(const float4*)&x[(size_t)n * D + c * 4];
    float4 v = make_float4(coef * xv.x, coef * xv.y, coef * xv.z, coef * xv.w);
    atomicAdd((float4*)&qstar[(size_t)b * 2 * D + D + c * 4], v);
}

__global__ void fc_kernel(const float* __restrict__ qstar,
                          const float* __restrict__ fw,
                          const float* __restrict__ fb,
                          float* __restrict__ out) {
    int warp = (int)(((size_t)blockIdx.x * blockDim.x + threadIdx.x) >> 5);
    int lane = threadIdx.x & 31;
    if (warp >= N_GRAPHS) return;
    float s = 0.f;
#pragma unroll
    for (int j = 0; j < (2 * D) / 32; j++)
        s += qstar[(size_t)warp * 2 * D + lane + j * 32] * fw[lane + j * 32];
#pragma unroll
    for (int o = 16; o; o >>= 1) s += __shfl_xor_sync(0xFFFFFFFFu, s, o);
    if (lane == 0) out[warp] = s + fb[0];
}

// ---------------- launch ----------------
extern "C" void kernel_launch(void* const* d_in, const int* in_sizes, int n_in,
                              void* d_out, int out_size) {
    const int* x_atoms = (const int*)d_in[0];
    const int* edge_index = (const int*)d_in[1];
    const int* edge_attr = (const int*)d_in[2];
    const int* batch = (const int*)d_in[3];
    const float* atom_emb = (const float*)d_in[4];
    const float* bond_emb = (const float*)d_in[5];
    const float* gin_w1 = (const float*)d_in[6];
    const float* gin_b1 = (const float*)d_in[7];
    const float* gin_w2 = (const float*)d_in[8];
    const float* gin_b2 = (const float*)d_in[9];
    const float* gru_wih = (const float*)d_in[10];
    const float* gru_whh = (const float*)d_in[11];
    const float* gru_bih = (const float*)d_in[12];
    const float* gru_bhh = (const float*)d_in[13];
    const float* lstm_wih = (const float*)d_in[14];
    const float* lstm_whh = (const float*)d_in[15];
    const float* lstm_bih = (const float*)d_in[16];
    const float* lstm_bhh = (const float*)d_in[17];
    const float* fc_w = (const float*)d_in[18];
    const float* fc_b = (const float*)d_in[19];
    float* out = (float*)d_out;

    float *hx0, *hx1, *e, *agg, *t, *xconv, *gi, *gh, *g1, *g2, *hs, *cs, *qstar, *prod, *mbuf, *norm;
    cudaGetSymbolAddress((void**)&hx0, g_hx0);
    cudaGetSymbolAddress((void**)&hx1, g_hx1);
    cudaGetSymbolAddress((void**)&e, g_e);
    cudaGetSymbolAddress((void**)&agg, g_agg);
    cudaGetSymbolAddress((void**)&t, g_t);
    cudaGetSymbolAddress((void**)&xconv, g_xconv);
    cudaGetSymbolAddress((void**)&gi, g_gi);
    cudaGetSymbolAddress((void**)&gh, g_gh);
    cudaGetSymbolAddress((void**)&g1, g_g1);
    cudaGetSymbolAddress((void**)&g2, g_g2);
    cudaGetSymbolAddress((void**)&hs, g_hs);
    cudaGetSymbolAddress((void**)&cs, g_cs);
    cudaGetSymbolAddress((void**)&qstar, g_qstar);
    cudaGetSymbolAddress((void**)&prod, g_prod);
    cudaGetSymbolAddress((void**)&mbuf, g_m);
    cudaGetSymbolAddress((void**)&norm, g_norm);

    const int TPB = 256;

    // encoders + S2S state init
    atom_encode_kernel<<<(N_NODES * 64) / TPB, TPB>>>(x_atoms, atom_emb, hx0, hx1);
    bond_encode_kernel<<<(N_EDGES * 64) / TPB, TPB>>>(edge_attr, bond_emb, e);
    cudaMemsetAsync(hs, 0, (size_t)N_GRAPHS * D * sizeof(float));
    cudaMemsetAsync(cs, 0, (size_t)N_GRAPHS * D * sizeof(float));
    cudaMemsetAsync(qstar, 0, (size_t)N_GRAPHS * 2 * D * sizeof(float));

    for (int layer = 0; layer < 3; layer++) {
        // agg = x, then agg[dst] += relu(x[src] + e)
        copy4_kernel<<<(N_NODES * D / 4) / TPB, TPB>>>(agg, hx1, (size_t)N_NODES * D / 4);
        edge_scatter_kernel<<<(N_EDGES * 64) / TPB, TPB>>>(edge_index, hx1, e, agg);
        // GIN MLP
        mma_gemm_kernel<false, true><<<dim3(512 / 128, N_NODES / 128), TPB>>>(
            agg, gin_w1, gin_b1, t, N_NODES, 512, 256);
        mma_gemm_kernel<false, false><<<dim3(256 / 128, N_NODES / 128), TPB>>>(
            t, gin_w2, gin_b2, xconv, N_NODES, 256, 512);
        // GRU layer 0
        mma_gemm_kernel<true, false><<<dim3(768 / 128, N_NODES / 128), TPB>>>(
            xconv, gru_wih, gru_bih, gi, N_NODES, 768, 256);
        mma_gemm_kernel<true, false><<<dim3(768 / 128, N_NODES / 128), TPB>>>(
            hx0, gru_whh, gru_bhh, gh, N_NODES, 768, 256);
        gru_gate_kernel<<<(N_NODES * D) / TPB, TPB>>>(gi, gh, hx0);
        // GRU layer 1
        mma_gemm_kernel<true, false><<<dim3(768 / 128, N_NODES / 128), TPB>>>(
            hx0, gru_wih + 768 * 256, gru_bih + 768, gi, N_NODES, 768, 256);
        mma_gemm_kernel<true, false><<<dim3(768 / 128, N_NODES / 128), TPB>>>(
            hx1, gru_whh + 768 * 256, gru_bhh + 768, gh, N_NODES, 768, 256);
        gru_gate_kernel<<<(N_NODES * D) / TPB, TPB>>>(gi, gh, hx1);
    }

    // Set2Set
    for (int step = 0; step < 3; step++) {
        mma_gemm_kernel<true, false><<<dim3(1024 / 128, N_GRAPHS / 128), TPB>>>(
            qstar, lstm_wih, lstm_bih, g1, N_GRAPHS, 1024, 512);
        mma_gemm_kernel<true, false><<<dim3(1024 / 128, N_GRAPHS / 128), TPB>>>(
            hs, lstm_whh, lstm_bhh, g2, N_GRAPHS, 1024, 256);
        lstm_gate_kernel<<<(N_GRAPHS * D) / TPB, TPB>>>(g1, g2, hs, cs);
        s2s_prep_kernel<<<(N_GRAPHS * D) / TPB, TPB>>>(qstar, hs, mbuf, norm);
        attn_prod_kernel<<<(N_NODES * 32) / TPB, TPB>>>(hs, hx1, batch, prod);
        attn_max_kernel<<<N_NODES / TPB, TPB>>>(batch, prod, mbuf);
        attn_expnorm_kernel<<<N_NODES / TPB, TPB>>>(batch, prod, mbuf, norm);
        attn_scatter_kernel<<<(N_NODES * 64) / TPB, TPB>>>(batch, prod, norm, hx1, qstar);
    }

    fc_kernel<<<(N_GRAPHS * 32) / TPB, TPB>>>(qstar, fc_w, fc_b, out);
}

// round 4
// speedup vs baseline: 2.5722x; 1.3224x over previous
#include <cuda_runtime.h>
#include <cuda_bf16.h>
#include <math.h>
#include <stdint.h>

#define N_NODES 131072
#define N_EDGES 524288
#define N_GRAPHS 4096
#define D 256
#define EPS 1e-10f

// ---------------- scratch (device globals; no allocation allowed) ----------
__device__ float g_hx0[N_NODES * D];
__device__ float g_hx1[N_NODES * D];          // aliases x
__device__ float g_e[N_EDGES * D];
__device__ float g_agg[N_NODES * D];
__device__ float g_t[N_NODES * 2 * D];
__device__ float g_xconv[N_NODES * D];
__device__ float g_gi[N_NODES * 3 * D];
__device__ float g_gh[N_NODES * 3 * D];
__device__ float g_g1[N_GRAPHS * 4 * D];
__device__ float g_g2[N_GRAPHS * 4 * D];
__device__ float g_hs[N_GRAPHS * D];
__device__ float g_cs[N_GRAPHS * D];
__device__ float g_qstar[N_GRAPHS * 2 * D];
__device__ float g_prod[N_NODES];
__device__ float g_m[N_GRAPHS];
__device__ float g_norm[N_GRAPHS];
__device__ float g_w1t[512 * 256];            // gin_w1^T  [N=512, K=256]
__device__ float g_w2t[256 * 512];            // gin_w2^T  [N=256, K=512]

// ---------------- helpers ----------------
__device__ __forceinline__ uint32_t smem_u32(const void* p) {
    uint32_t a;
    asm("{ .reg .u64 t; cvta.to.shared.u64 t, %1; cvt.u32.u64 %0, t; }" : "=r"(a) : "l"(p));
    return a;
}
__device__ __forceinline__ void cp_async16(uint32_t saddr, const void* gptr) {
    asm volatile("cp.async.cg.shared.global [%0], [%1], 16;"
                 :: "r"(saddr), "l"(gptr) : "memory");
}
__device__ __forceinline__ void atomicMaxFloat(float* addr, float val) {
    int* ia = (int*)addr;
    int cur = __float_as_int(*(volatile float*)addr);
    while (__int_as_float(cur) < val) {
        int old = atomicCAS(ia, cur, __float_as_int(val));
        if (old == cur) break;
        cur = old;
    }
}
__device__ __forceinline__ float sigmoidf_(float x) { return 1.0f / (1.0f + expf(-x)); }
__device__ __forceinline__ uint32_t to_tf32(float x) {
    uint32_t u;
    asm("cvt.rna.tf32.f32 %0, %1;" : "=r"(u) : "f"(x));
    return u;
}
__device__ __forceinline__ void mma_tf32(float* c, const uint32_t* a, const uint32_t* b) {
    asm volatile(
        "mma.sync.aligned.m16n8k8.row.col.f32.tf32.tf32.f32 "
        "{%0,%1,%2,%3}, {%4,%5,%6,%7}, {%8,%9}, {%0,%1,%2,%3};"
        : "+f"(c[0]), "+f"(c[1]), "+f"(c[2]), "+f"(c[3])
        : "r"(a[0]), "r"(a[1]), "r"(a[2]), "r"(a[3]), "r"(b[0]), "r"(b[1]));
}

// ---------------- tf32 tensor-core GEMM: C[M,N] = A[M,K] @ B^T + bias ------
// A [M,K] row-major, B [N,K] row-major. M%128==0, N%256==0, K%32==0.
// Block tile 128x256, BK=32, 8 warps (2m x 4n), warp tile 64x64.
// cp.async double-buffered staging, padded smem (stride 36 floats, conflict-free).
static constexpr int GEMM_AST = 36;
static constexpr int GEMM_ASZ = 128 * GEMM_AST;       // floats
static constexpr int GEMM_BSZ = 256 * GEMM_AST;
static constexpr int GEMM_BUF = GEMM_ASZ + GEMM_BSZ;  // 13824 floats = 55296 B
static constexpr int GEMM_SMEM = 2 * GEMM_BUF * 4;    // 110592 B

template <bool RELU>
__global__ __launch_bounds__(256, 1) void mma_gemm_kernel(
    const float* __restrict__ A, const float* __restrict__ B,
    const float* __restrict__ bias, float* __restrict__ C,
    int M, int N, int K) {
    extern __shared__ float sm[];
    const int tid = threadIdx.x;
    const int lane = tid & 31;
    const int warp = tid >> 5;
    const int wm = warp & 1;          // 2 warps along M
    const int wn = warp >> 1;         // 4 warps along N
    const int m0 = blockIdx.y * 128;
    const int n0 = blockIdx.x * 256;
    const uint32_t sbase = smem_u32(sm);

    float acc[4][8][4];
#pragma unroll
    for (int i = 0; i < 4; i++)
#pragma unroll
        for (int j = 0; j < 8; j++)
#pragma unroll
            for (int r = 0; r < 4; r++) acc[i][j][r] = 0.f;

    const int niter = K >> 5;

    // stage buffer `buf` with k-chunk k0i
    auto stage = [&](int buf, int k0i) {
        uint32_t abase = sbase + (uint32_t)buf * GEMM_BUF * 4;
        uint32_t bbase = abase + GEMM_ASZ * 4;
        const float* Ag = A + (size_t)m0 * K + k0i * 32;
        const float* Bg = B + (size_t)n0 * K + k0i * 32;
#pragma unroll
        for (int i = 0; i < 4; i++) {
            int v = tid + i * 256;
            int r = v >> 3, c = v & 7;
            cp_async16(abase + (uint32_t)(r * GEMM_AST + c * 4) * 4,
                       Ag + (size_t)r * K + c * 4);
        }
#pragma unroll
        for (int i = 0; i < 8; i++) {
            int v = tid + i * 256;
            int r = v >> 3, c = v & 7;
            cp_async16(bbase + (uint32_t)(r * GEMM_AST + c * 4) * 4,
                       Bg + (size_t)r * K + c * 4);
        }
    };

    stage(0, 0);
    asm volatile("cp.async.commit_group;" ::: "memory");

    for (int k0i = 0; k0i < niter; k0i++) {
        if (k0i + 1 < niter) stage((k0i + 1) & 1, k0i + 1);
        asm volatile("cp.async.commit_group;" ::: "memory");
        asm volatile("cp.async.wait_group 1;" ::: "memory");
        __syncthreads();

        const float* As = sm + (k0i & 1) * GEMM_BUF;
        const float* Bs = As + GEMM_ASZ;

#pragma unroll
        for (int ks = 0; ks < 4; ks++) {
            int kb = ks * 8 + (lane & 3);
            uint32_t a[4][4];
#pragma unroll
            for (int i = 0; i < 4; i++) {
                int mr = wm * 64 + i * 16 + (lane >> 2);
                a[i][0] = to_tf32(As[mr * GEMM_AST + kb]);
                a[i][1] = to_tf32(As[(mr + 8) * GEMM_AST + kb]);
                a[i][2] = to_tf32(As[mr * GEMM_AST + kb + 4]);
                a[i][3] = to_tf32(As[(mr + 8) * GEMM_AST + kb + 4]);
            }
            uint32_t b[8][2];
#pragma unroll
            for (int j = 0; j < 8; j++) {
                int nc = wn * 64 + j * 8 + (lane >> 2);
                b[j][0] = to_tf32(Bs[nc * GEMM_AST + kb]);
                b[j][1] = to_tf32(Bs[nc * GEMM_AST + kb + 4]);
            }
#pragma unroll
            for (int i = 0; i < 4; i++)
#pragma unroll
                for (int j = 0; j < 8; j++) mma_tf32(acc[i][j], a[i], b[j]);
        }
        __syncthreads();
    }

    // epilogue
#pragma unroll
    for (int i = 0; i < 4; i++) {
        int mr = m0 + wm * 64 + i * 16 + (lane >> 2);
#pragma unroll
        for (int j = 0; j < 8; j++) {
            int nc = n0 + wn * 64 + j * 8 + (lane & 3) * 2;
            float b0 = bias[nc], b1 = bias[nc + 1];
            float v0 = acc[i][j][0] + b0;
            float v1 = acc[i][j][1] + b1;
            float v2 = acc[i][j][2] + b0;
            float v3 = acc[i][j][3] + b1;
            if (RELU) {
                v0 = fmaxf(v0, 0.f); v1 = fmaxf(v1, 0.f);
                v2 = fmaxf(v2, 0.f); v3 = fmaxf(v3, 0.f);
            }
            *(float2*)&C[(size_t)mr * N + nc] = make_float2(v0, v1);
            *(float2*)&C[(size_t)(mr + 8) * N + nc] = make_float2(v2, v3);
        }
    }
}

// ---------------- weight transpose (tiny, once per launch) ----------------
__global__ void transpose_kernel(const float* __restrict__ in, float* __restrict__ out,
                                 int R, int C) {
    __shared__ float t[32][33];
    int c0 = blockIdx.x * 32, r0 = blockIdx.y * 32;
    for (int i = threadIdx.y; i < 32; i += 8)
        t[i][threadIdx.x] = in[(size_t)(r0 + i) * C + c0 + threadIdx.x];
    __syncthreads();
    for (int i = threadIdx.y; i < 32; i += 8)
        out[(size_t)(c0 + i) * R + r0 + threadIdx.x] = t[threadIdx.x][i];
}

// ---------------- encoders ----------------
__global__ void atom_encode_kernel(const int* __restrict__ xa,
                                   const float* __restrict__ emb,
                                   float* __restrict__ hx0, float* __restrict__ hx1) {
    size_t idx = (size_t)blockIdx.x * blockDim.x + threadIdx.x;
    if (idx >= (size_t)N_NODES * 64) return;
    int n = (int)(idx >> 6);
    int c = (int)(idx & 63);
    float4 acc = make_float4(0.f, 0.f, 0.f, 0.f);
#pragma unroll
    for (int i = 0; i < 9; i++) {
        int t = xa[n * 9 + i];
        const float4 v = *(const float4*)&emb[((size_t)(i * 120 + t)) * D + c * 4];
        acc.x += v.x; acc.y += v.y; acc.z += v.z; acc.w += v.w;
    }
    *(float4*)&hx0[(size_t)n * D + c * 4] = acc;
    *(float4*)&hx1[(size_t)n * D + c * 4] = acc;
}

__global__ void bond_encode_kernel(const int* __restrict__ ea,
                                   const float* __restrict__ emb,
                                   float* __restrict__ e_out) {
    size_t idx = (size_t)blockIdx.x * blockDim.x + threadIdx.x;
    if (idx >= (size_t)N_EDGES * 64) return;
    int n = (int)(idx >> 6);
    int c = (int)(idx & 63);
    float4 acc = make_float4(0.f, 0.f, 0.f, 0.f);
#pragma unroll
    for (int i = 0; i < 3; i++) {
        int t = ea[n * 3 + i];
        const float4 v = *(const float4*)&emb[((size_t)(i * 6 + t)) * D + c * 4];
        acc.x += v.x; acc.y += v.y; acc.z += v.z; acc.w += v.w;
    }
    *(float4*)&e_out[(size_t)n * D + c * 4] = acc;
}

// ---------------- elementwise ----------------
__global__ void copy4_kernel(float* __restrict__ dst, const float* __restrict__ src, size_t n4) {
    size_t i = (size_t)blockIdx.x * blockDim.x + threadIdx.x;
    if (i < n4) ((float4*)dst)[i] = ((const float4*)src)[i];
}

__global__ void edge_scatter_kernel(const int* __restrict__ ei,
                                    const float* __restrict__ x,
                                    const float* __restrict__ e,
                                    float* __restrict__ agg) {
    size_t idx = (size_t)blockIdx.x * blockDim.x + threadIdx.x;
    if (idx >= (size_t)N_EDGES * 64) return;
    int ed = (int)(idx >> 6);
    int c = (int)(idx & 63);
    int s = ei[ed];
    int d = ei[N_EDGES + ed];
    float4 xv = *(const float4*)&x[(size_t)s * D + c * 4];
    float4 ev = *(const float4*)&e[(size_t)ed * D + c * 4];
    float4 m;
    m.x = fmaxf(xv.x + ev.x, 0.f);
    m.y = fmaxf(xv.y + ev.y, 0.f);
    m.z = fmaxf(xv.z + ev.z, 0.f);
    m.w = fmaxf(xv.w + ev.w, 0.f);
    atomicAdd((float4*)&agg[(size_t)d * D + c * 4], m);
}

// ---------------- GRU / LSTM gates ----------------
__global__ void gru_gate_kernel(const float* __restrict__ gi,
                                const float* __restrict__ gh,
                                float* __restrict__ hx) {
    size_t idx = (size_t)blockIdx.x * blockDim.x + threadIdx.x;
    if (idx >= (size_t)N_NODES * D) return;
    int n = (int)(idx >> 8);
    int d = (int)(idx & 255);
    size_t base = (size_t)n * 3 * D + d;
    float ir = gi[base], iz = gi[base + D], in_ = gi[base + 2 * D];
    float hr = gh[base], hz = gh[base + D], hn = gh[base + 2 * D];
    float r = sigmoidf_(ir + hr);
    float z = sigmoidf_(iz + hz);
    float nn = tanhf(in_ + r * hn);
    float hprev = hx[idx];
    hx[idx] = (1.0f - z) * nn + z * hprev;
}

__global__ void lstm_gate_kernel(const float* __restrict__ g1,
                                 const float* __restrict__ g2,
                                 float* __restrict__ hs, float* __restrict__ cs) {
    size_t idx = (size_t)blockIdx.x * blockDim.x + threadIdx.x;
    if (idx >= (size_t)N_GRAPHS * D) return;
    int b = (int)(idx >> 8);
    int d = (int)(idx & 255);
    size_t base = (size_t)b * 4 * D + d;
    float ig = sigmoidf_(g1[base] + g2[base]);
    float fg = sigmoidf_(g1[base + D] + g2[base + D]);
    float gg = tanhf(g1[base + 2 * D] + g2[base + 2 * D]);
    float og = sigmoidf_(g1[base + 3 * D] + g2[base + 3 * D]);
    float c = fg * cs[idx] + ig * gg;
    cs[idx] = c;
    hs[idx] = og * tanhf(c);
}

// ---------------- Set2Set attention ----------------
__global__ void s2s_prep_kernel(float* __restrict__ qstar,
                                const float* __restrict__ hs,
                                float* __restrict__ m, float* __restrict__ norm) {
    size_t i = (size_t)blockIdx.x * blockDim.x + threadIdx.x;
    if (i < N_GRAPHS) { m[i] = -INFINITY; norm[i] = 0.f; }
    if (i < (size_t)N_GRAPHS * D) {
        int b = (int)(i >> 8);
        int d = (int)(i & 255);
        qstar[(size_t)b * 2 * D + d] = hs[i];
        qstar[(size_t)b * 2 * D + D + d] = 0.f;
    }
}

__global__ void attn_prod_kernel(const float* __restrict__ hs,
                                 const float* __restrict__ x,
                                 const int* __restrict__ batch,
                                 float* __restrict__ prod) {
    int warp = (int)(((size_t)blockIdx.x * blockDim.x + threadIdx.x) >> 5);
    int lane = threadIdx.x & 31;
    if (warp >= N_NODES) return;
    int b = batch[warp];
    const float* q = hs + (size_t)b * D;
    const float* xv = x + (size_t)warp * D;
    float s = 0.f;
#pragma unroll
    for (int j = 0; j < D / 32; j++) s += q[lane + j * 32] * xv[lane + j * 32];
#pragma unroll
    for (int o = 16; o; o >>= 1) s += __shfl_xor_sync(0xFFFFFFFFu, s, o);
    if (lane == 0) prod[warp] = s;
}

__global__ void attn_max_kernel(const int* __restrict__ batch,
                                const float* __restrict__ prod,
                                float* __restrict__ m) {
    int n = (int)((size_t)blockIdx.x * blockDim.x + threadIdx.x);
    if (n >= N_NODES) return;
    atomicMaxFloat(&m[batch[n]], prod[n]);
}

__global__ void attn_expnorm_kernel(const int* __restrict__ batch,
                                    float* __restrict__ prod,
                                    const float* __restrict__ m,
                                    float* __restrict__ norm) {
    int n = (int)((size_t)blockIdx.x * blockDim.x + threadIdx.x);
    if (n >= N_NODES) return;
    int b = batch[n];
    float a = expf(prod[n] - m[b]);
    prod[n] = a;
    atomicAdd(&norm[b], a);
}

__global__ void attn_scatter_kernel(const int* __restrict__ batch,
                                    const float* __restrict__ prod,
                                    const float* __restrict__ norm,
                                    const float* __restrict__ x,
                                    float* __restrict__ qstar) {
    size_t idx = (size_t)blockIdx.x * blockDim.x + threadIdx.x;
    if (idx >= (size_t)N_NODES * 64) return;
    int n = (int)(idx >> 6);
    int c = (int)(idx & 63);
    int b = batch[n];
    float coef = prod[n] / (norm[b] + EPS);
    float4 xv = *(const float4*)&x[(size_t)n * D + c * 4];
    float4 v = make_float4(coef * xv.x, coef * xv.y, coef * xv.z, coef * xv.w);
    atomicAdd((float4*)&qstar[(size_t)b * 2 * D + D + c * 4], v);
}

__global__ void fc_kernel(const float* __restrict__ qstar,
                          const float* __restrict__ fw,
                          const float* __restrict__ fb,
                          float* __restrict__ out) {
    int warp = (int)(((size_t)blockIdx.x * blockDim.x + threadIdx.x) >> 5);
    int lane = threadIdx.x & 31;
    if (warp >= N_GRAPHS) return;
    float s = 0.f;
#pragma unroll
    for (int j = 0; j < (2 * D) / 32; j++)
        s += qstar[(size_t)warp * 2 * D + lane + j * 32] * fw[lane + j * 32];
#pragma unroll
    for (int o = 16; o; o >>= 1) s += __shfl_xor_sync(0xFFFFFFFFu, s, o);
    if (lane == 0) out[warp] = s + fb[0];
}

// ---------------- launch ----------------
extern "C" void kernel_launch(void* const* d_in, const int* in_sizes, int n_in,
                              void* d_out, int out_size) {
    const int* x_atoms = (const int*)d_in[0];
    const int* edge_index = (const int*)d_in[1];
    const int* edge_attr = (const int*)d_in[2];
    const int* batch = (const int*)d_in[3];
    const float* atom_emb = (const float*)d_in[4];
    const float* bond_emb = (const float*)d_in[5];
    const float* gin_w1 = (const float*)d_in[6];
    const float* gin_b1 = (const float*)d_in[7];
    const float* gin_w2 = (const float*)d_in[8];
    const float* gin_b2 = (const float*)d_in[9];
    const float* gru_wih = (const float*)d_in[10];
    const float* gru_whh = (const float*)d_in[11];
    const float* gru_bih = (const float*)d_in[12];
    const float* gru_bhh = (const float*)d_in[13];
    const float* lstm_wih = (const float*)d_in[14];
    const float* lstm_whh = (const float*)d_in[15];
    const float* lstm_bih = (const float*)d_in[16];
    const float* lstm_bhh = (const float*)d_in[17];
    const float* fc_w = (const float*)d_in[18];
    const float* fc_b = (const float*)d_in[19];
    float* out = (float*)d_out;

    float *hx0, *hx1, *e, *agg, *t, *xconv, *gi, *gh, *g1, *g2, *hs, *cs, *qstar,
        *prod, *mbuf, *norm, *w1t, *w2t;
    cudaGetSymbolAddress((void**)&hx0, g_hx0);
    cudaGetSymbolAddress((void**)&hx1, g_hx1);
    cudaGetSymbolAddress((void**)&e, g_e);
    cudaGetSymbolAddress((void**)&agg, g_agg);
    cudaGetSymbolAddress((void**)&t, g_t);
    cudaGetSymbolAddress((void**)&xconv, g_xconv);
    cudaGetSymbolAddress((void**)&gi, g_gi);
    cudaGetSymbolAddress((void**)&gh, g_gh);
    cudaGetSymbolAddress((void**)&g1, g_g1);
    cudaGetSymbolAddress((void**)&g2, g_g2);
    cudaGetSymbolAddress((void**)&hs, g_hs);
    cudaGetSymbolAddress((void**)&cs, g_cs);
    cudaGetSymbolAddress((void**)&qstar, g_qstar);
    cudaGetSymbolAddress((void**)&prod, g_prod);
    cudaGetSymbolAddress((void**)&mbuf, g_m);
    cudaGetSymbolAddress((void**)&norm, g_norm);
    cudaGetSymbolAddress((void**)&w1t, g_w1t);
    cudaGetSymbolAddress((void**)&w2t, g_w2t);

    cudaFuncSetAttribute(mma_gemm_kernel<false>,
                         cudaFuncAttributeMaxDynamicSharedMemorySize, GEMM_SMEM);
    cudaFuncSetAttribute(mma_gemm_kernel<true>,
                         cudaFuncAttributeMaxDynamicSharedMemorySize, GEMM_SMEM);

    const int TPB = 256;

    transpose_kernel<<<dim3(512 / 32, 256 / 32), dim3(32, 8)>>>(gin_w1, w1t, 256, 512);
    transpose_kernel<<<dim3(256 / 32, 512 / 32), dim3(32, 8)>>>(gin_w2, w2t, 512, 256);

    atom_encode_kernel<<<(N_NODES * 64) / TPB, TPB>>>(x_atoms, atom_emb, hx0, hx1);
    bond_encode_kernel<<<(N_EDGES * 64) / TPB, TPB>>>(edge_attr, bond_emb, e);
    cudaMemsetAsync(hs, 0, (size_t)N_GRAPHS * D * sizeof(float));
    cudaMemsetAsync(cs, 0, (size_t)N_GRAPHS * D * sizeof(float));
    cudaMemsetAsync(qstar, 0, (size_t)N_GRAPHS * 2 * D * sizeof(float));

    for (int layer = 0; layer < 3; layer++) {
        copy4_kernel<<<(N_NODES * D / 4) / TPB, TPB>>>(agg, hx1, (size_t)N_NODES * D / 4);
        edge_scatter_kernel<<<(N_EDGES * 64) / TPB, TPB>>>(edge_index, hx1, e, agg);
        // GIN MLP (weights pre-transposed to [N,K])
        mma_gemm_kernel<true><<<dim3(512 / 256, N_NODES / 128), TPB, GEMM_SMEM>>>(
            agg, w1t, gin_b1, t, N_NODES, 512, 256);
        mma_gemm_kernel<false><<<dim3(256 / 256, N_NODES / 128), TPB, GEMM_SMEM>>>(
            t, w2t, gin_b2, xconv, N_NODES, 256, 512);
        // GRU layer 0
        mma_gemm_kernel<false><<<dim3(768 / 256, N_NODES / 128), TPB, GEMM_SMEM>>>(
            xconv, gru_wih, gru_bih, gi, N_NODES, 768, 256);
        mma_gemm_kernel<false><<<dim3(768 / 256, N_NODES / 128), TPB, GEMM_SMEM>>>(
            hx0, gru_whh, gru_bhh, gh, N_NODES, 768, 256);
        gru_gate_kernel<<<(N_NODES * D) / TPB, TPB>>>(gi, gh, hx0);
        // GRU layer 1
        mma_gemm_kernel<false><<<dim3(768 / 256, N_NODES / 128), TPB, GEMM_SMEM>>>(
            hx0, gru_wih + 768 * 256, gru_bih + 768, gi, N_NODES, 768, 256);
        mma_gemm_kernel<false><<<dim3(768 / 256, N_NODES / 128), TPB, GEMM_SMEM>>>(
            hx1, gru_whh + 768 * 256, gru_bhh + 768, gh, N_NODES, 768, 256);
        gru_gate_kernel<<<(N_NODES * D) / TPB, TPB>>>(gi, gh, hx1);
    }

    for (int step = 0; step < 3; step++) {
        mma_gemm_kernel<false><<<dim3(1024 / 256, N_GRAPHS / 128), TPB, GEMM_SMEM>>>(
            qstar, lstm_wih, lstm_bih, g1, N_GRAPHS, 1024, 512);
        mma_gemm_kernel<false><<<dim3(1024 / 256, N_GRAPHS / 128), TPB, GEMM_SMEM>>>(
            hs, lstm_whh, lstm_bhh, g2, N_GRAPHS, 1024, 256);
        lstm_gate_kernel<<<(N_GRAPHS * D) / TPB, TPB>>>(g1, g2, hs, cs);
        s2s_prep_kernel<<<(N_GRAPHS * D) / TPB, TPB>>>(qstar, hs, mbuf, norm);
        attn_prod_kernel<<<(N_NODES * 32) / TPB, TPB>>>(hs, hx1, batch, prod);
        attn_max_kernel<<<N_NODES / TPB, TPB>>>(batch, prod, mbuf);
        attn_expnorm_kernel<<<N_NODES / TPB, TPB>>>(batch, prod, mbuf, norm);
        attn_scatter_kernel<<<(N_NODES * 64) / TPB, TPB>>>(batch, prod, norm, hx1, qstar);
    }

    fc_kernel<<<(N_GRAPHS * 32) / TPB, TPB>>>(qstar, fc_w, fc_b, out);
}

// round 5
// speedup vs baseline: 2.7409x; 1.0656x over previous
#include <cuda_runtime.h>
#include <cuda_bf16.h>
#include <math.h>
#include <stdint.h>

#define N_NODES 131072
#define N_EDGES 524288
#define N_GRAPHS 4096
#define D 256
#define EPS 1e-10f

// ---------------- scratch (device globals; no allocation allowed) ----------
__device__ float g_hx0[N_NODES * D];
__device__ float g_hx1[N_NODES * D];          // aliases x
__device__ float g_e[N_EDGES * D];
__device__ float g_agg[N_NODES * D];
__device__ float g_t[N_NODES * 2 * D];
__device__ float g_xconv[N_NODES * D];
__device__ float g_gi[N_NODES * 3 * D];
__device__ float g_gh[N_NODES * 3 * D];
__device__ float g_g1[N_GRAPHS * 4 * D];
__device__ float g_g2[N_GRAPHS * 4 * D];
__device__ float g_hs[N_GRAPHS * D];
__device__ float g_cs[N_GRAPHS * D];
__device__ float g_qstar[N_GRAPHS * 2 * D];
__device__ float g_prod[N_NODES];
__device__ float g_m[N_GRAPHS];
__device__ float g_norm[N_GRAPHS];
__device__ float g_w1t[512 * 256];            // gin_w1^T  [N=512, K=256]
__device__ float g_w2t[256 * 512];            // gin_w2^T  [N=256, K=512]

// ---------------- helpers ----------------
__device__ __forceinline__ void atomicMaxFloat(float* addr, float val) {
    int* ia = (int*)addr;
    int cur = __float_as_int(*(volatile float*)addr);
    while (__int_as_float(cur) < val) {
        int old = atomicCAS(ia, cur, __float_as_int(val));
        if (old == cur) break;
        cur = old;
    }
}
__device__ __forceinline__ float sigmoidf_(float x) { return 1.0f / (1.0f + expf(-x)); }
__device__ __forceinline__ uint32_t to_tf32(float x) {
    uint32_t u;
    asm("cvt.rna.tf32.f32 %0, %1;" : "=r"(u) : "f"(x));
    return u;
}
__device__ __forceinline__ void mma_tf32(float* c, const uint32_t* a, const uint32_t* b) {
    asm volatile(
        "mma.sync.aligned.m16n8k8.row.col.f32.tf32.tf32.f32 "
        "{%0,%1,%2,%3}, {%4,%5,%6,%7}, {%8,%9}, {%0,%1,%2,%3};"
        : "+f"(c[0]), "+f"(c[1]), "+f"(c[2]), "+f"(c[3])
        : "r"(a[0]), "r"(a[1]), "r"(a[2]), "r"(a[3]), "r"(b[0]), "r"(b[1]));
}

// ---------------- tf32 tensor-core GEMM: C[M,N] = A[M,K] @ B^T + bias ------
// A [M,K] row-major, B [N,K] row-major. M%128==0, N%256==0, K%32==0.
// Block tile 128x256, BK=32, 8 warps (2m x 4n), warp tile 64x64.
// LDG->reg prefetch double buffering; cvt to tf32 at STS (inner loop LDS+MMA only).
static constexpr int GEMM_AST = 36;
static constexpr int GEMM_ASZ = 128 * GEMM_AST;       // words
static constexpr int GEMM_BSZ = 256 * GEMM_AST;
static constexpr int GEMM_BUF = GEMM_ASZ + GEMM_BSZ;  // 13824 words
static constexpr int GEMM_SMEM = 2 * GEMM_BUF * 4;    // 110592 B

template <bool RELU>
__global__ __launch_bounds__(256, 1) void mma_gemm_kernel(
    const float* __restrict__ A, const float* __restrict__ B,
    const float* __restrict__ bias, float* __restrict__ C,
    int M, int N, int K) {
    extern __shared__ uint32_t sm[];
    const int tid = threadIdx.x;
    const int lane = tid & 31;
    const int warp = tid >> 5;
    const int wm = warp & 1;          // 2 warps along M
    const int wn = warp >> 1;         // 4 warps along N
    const int m0 = blockIdx.y * 128;
    const int n0 = blockIdx.x * 256;

    const int ar = tid >> 3, ac = tid & 7;   // staging coords

    float acc[4][8][4];
#pragma unroll
    for (int i = 0; i < 4; i++)
#pragma unroll
        for (int j = 0; j < 8; j++)
#pragma unroll
            for (int r = 0; r < 4; r++) acc[i][j][r] = 0.f;

    const int niter = K >> 5;
    float4 pa[4], pb[8];

#define LDG_TILE(k0i)                                                              \
    do {                                                                           \
        const float* Ag = A + (size_t)m0 * K + (k0i) * 32;                         \
        const float* Bg = B + (size_t)n0 * K + (k0i) * 32;                         \
        _Pragma("unroll")                                                          \
        for (int i = 0; i < 4; i++)                                                \
            pa[i] = *(const float4*)&Ag[(size_t)(ar + i * 32) * K + ac * 4];       \
        _Pragma("unroll")                                                          \
        for (int i = 0; i < 8; i++)                                                \
            pb[i] = *(const float4*)&Bg[(size_t)(ar + i * 32) * K + ac * 4];       \
    } while (0)

#define STS_TILE(buf)                                                              \
    do {                                                                           \
        uint32_t* As_ = sm + (buf) * GEMM_BUF;                                     \
        uint32_t* Bs_ = As_ + GEMM_ASZ;                                            \
        _Pragma("unroll")                                                          \
        for (int i = 0; i < 4; i++) {                                              \
            uint32_t* p = &As_[(ar + i * 32) * GEMM_AST + ac * 4];                 \
            p[0] = to_tf32(pa[i].x); p[1] = to_tf32(pa[i].y);                      \
            p[2] = to_tf32(pa[i].z); p[3] = to_tf32(pa[i].w);                      \
        }                                                                          \
        _Pragma("unroll")                                                          \
        for (int i = 0; i < 8; i++) {                                              \
            uint32_t* p = &Bs_[(ar + i * 32) * GEMM_AST + ac * 4];                 \
            p[0] = to_tf32(pb[i].x); p[1] = to_tf32(pb[i].y);                      \
            p[2] = to_tf32(pb[i].z); p[3] = to_tf32(pb[i].w);                      \
        }                                                                          \
    } while (0)

    LDG_TILE(0);
    STS_TILE(0);
    __syncthreads();

    for (int k0i = 0; k0i < niter; k0i++) {
        if (k0i + 1 < niter) LDG_TILE(k0i + 1);

        const uint32_t* As = sm + (k0i & 1) * GEMM_BUF;
        const uint32_t* Bs = As + GEMM_ASZ;
#pragma unroll
        for (int ks = 0; ks < 4; ks++) {
            int kb = ks * 8 + (lane & 3);
            uint32_t a[4][4];
#pragma unroll
            for (int i = 0; i < 4; i++) {
                int mr = wm * 64 + i * 16 + (lane >> 2);
                a[i][0] = As[mr * GEMM_AST + kb];
                a[i][1] = As[(mr + 8) * GEMM_AST + kb];
                a[i][2] = As[mr * GEMM_AST + kb + 4];
                a[i][3] = As[(mr + 8) * GEMM_AST + kb + 4];
            }
            uint32_t b[8][2];
#pragma unroll
            for (int j = 0; j < 8; j++) {
                int nc = wn * 64 + j * 8 + (lane >> 2);
                b[j][0] = Bs[nc * GEMM_AST + kb];
                b[j][1] = Bs[nc * GEMM_AST + kb + 4];
            }
#pragma unroll
            for (int i = 0; i < 4; i++)
#pragma unroll
                for (int j = 0; j < 8; j++) mma_tf32(acc[i][j], a[i], b[j]);
        }
        if (k0i + 1 < niter) {
            __syncthreads();
            STS_TILE((k0i + 1) & 1);
            __syncthreads();
        }
    }

    // epilogue
#pragma unroll
    for (int i = 0; i < 4; i++) {
        int mr = m0 + wm * 64 + i * 16 + (lane >> 2);
#pragma unroll
        for (int j = 0; j < 8; j++) {
            int nc = n0 + wn * 64 + j * 8 + (lane & 3) * 2;
            float b0 = bias[nc], b1 = bias[nc + 1];
            float v0 = acc[i][j][0] + b0;
            float v1 = acc[i][j][1] + b1;
            float v2 = acc[i][j][2] + b0;
            float v3 = acc[i][j][3] + b1;
            if (RELU) {
                v0 = fmaxf(v0, 0.f); v1 = fmaxf(v1, 0.f);
                v2 = fmaxf(v2, 0.f); v3 = fmaxf(v3, 0.f);
            }
            *(float2*)&C[(size_t)mr * N + nc] = make_float2(v0, v1);
            *(float2*)&C[(size_t)(mr + 8) * N + nc] = make_float2(v2, v3);
        }
    }
#undef LDG_TILE
#undef STS_TILE
}

// ---------------- weight transpose (tiny, once per launch) ----------------
__global__ void transpose_kernel(const float* __restrict__ in, float* __restrict__ out,
                                 int R, int C) {
    __shared__ float t[32][33];
    int c0 = blockIdx.x * 32, r0 = blockIdx.y * 32;
    for (int i = threadIdx.y; i < 32; i += 8)
        t[i][threadIdx.x] = in[(size_t)(r0 + i) * C + c0 + threadIdx.x];
    __syncthreads();
    for (int i = threadIdx.y; i < 32; i += 8)
        out[(size_t)(c0 + i) * R + r0 + threadIdx.x] = t[threadIdx.x][i];
}

// ---------------- encoders ----------------
__global__ void atom_encode_kernel(const int* __restrict__ xa,
                                   const float* __restrict__ emb,
                                   float* __restrict__ hx0, float* __restrict__ hx1,
                                   float* __restrict__ agg) {
    size_t idx = (size_t)blockIdx.x * blockDim.x + threadIdx.x;
    if (idx >= (size_t)N_NODES * 64) return;
    int n = (int)(idx >> 6);
    int c = (int)(idx & 63);
    float4 acc = make_float4(0.f, 0.f, 0.f, 0.f);
#pragma unroll
    for (int i = 0; i < 9; i++) {
        int t = xa[n * 9 + i];
        const float4 v = *(const float4*)&emb[((size_t)(i * 120 + t)) * D + c * 4];
        acc.x += v.x; acc.y += v.y; acc.z += v.z; acc.w += v.w;
    }
    *(float4*)&hx0[(size_t)n * D + c * 4] = acc;
    *(float4*)&hx1[(size_t)n * D + c * 4] = acc;
    *(float4*)&agg[(size_t)n * D + c * 4] = acc;
}

__global__ void bond_encode_kernel(const int* __restrict__ ea,
                                   const float* __restrict__ emb,
                                   float* __restrict__ e_out) {
    size_t idx = (size_t)blockIdx.x * blockDim.x + threadIdx.x;
    if (idx >= (size_t)N_EDGES * 64) return;
    int n = (int)(idx >> 6);
    int c = (int)(idx & 63);
    float4 acc = make_float4(0.f, 0.f, 0.f, 0.f);
#pragma unroll
    for (int i = 0; i < 3; i++) {
        int t = ea[n * 3 + i];
        const float4 v = *(const float4*)&emb[((size_t)(i * 6 + t)) * D + c * 4];
        acc.x += v.x; acc.y += v.y; acc.z += v.z; acc.w += v.w;
    }
    *(float4*)&e_out[(size_t)n * D + c * 4] = acc;
}

// ---------------- edge scatter ----------------
__global__ void edge_scatter_kernel(const int* __restrict__ ei,
                                    const float* __restrict__ x,
                                    const float* __restrict__ e,
                                    float* __restrict__ agg) {
    size_t idx = (size_t)blockIdx.x * blockDim.x + threadIdx.x;
    if (idx >= (size_t)N_EDGES * 64) return;
    int ed = (int)(idx >> 6);
    int c = (int)(idx & 63);
    int s = ei[ed];
    int d = ei[N_EDGES + ed];
    float4 xv = *(const float4*)&x[(size_t)s * D + c * 4];
    float4 ev = *(const float4*)&e[(size_t)ed * D + c * 4];
    float4 m;
    m.x = fmaxf(xv.x + ev.x, 0.f);
    m.y = fmaxf(xv.y + ev.y, 0.f);
    m.z = fmaxf(xv.z + ev.z, 0.f);
    m.w = fmaxf(xv.w + ev.w, 0.f);
    atomicAdd((float4*)&agg[(size_t)d * D + c * 4], m);
}

// ---------------- GRU / LSTM gates ----------------
// vectorized x4; optionally also writes agg (next layer's x-preload)
__global__ void gru_gate_kernel(const float* __restrict__ gi,
                                const float* __restrict__ gh,
                                float* __restrict__ hx,
                                float* __restrict__ agg_out) {
    size_t idx = (size_t)blockIdx.x * blockDim.x + threadIdx.x;
    if (idx >= (size_t)N_NODES * 64) return;
    int n = (int)(idx >> 6);
    int c = (int)(idx & 63);
    size_t base = (size_t)n * 3 * D + c * 4;
    float4 ir = *(const float4*)&gi[base];
    float4 iz = *(const float4*)&gi[base + D];
    float4 in_ = *(const float4*)&gi[base + 2 * D];
    float4 hr = *(const float4*)&gh[base];
    float4 hz = *(const float4*)&gh[base + D];
    float4 hn = *(const float4*)&gh[base + 2 * D];
    size_t hidx = (size_t)n * D + c * 4;
    float4 hp = *(const float4*)&hx[hidx];
    float4 o;
#define GRU1(X)                                                        \
    {                                                                  \
        float r = sigmoidf_(ir.X + hr.X);                              \
        float z = sigmoidf_(iz.X + hz.X);                              \
        float nn = tanhf(in_.X + r * hn.X);                            \
        o.X = (1.0f - z) * nn + z * hp.X;                              \
    }
    GRU1(x) GRU1(y) GRU1(z) GRU1(w)
#undef GRU1
    *(float4*)&hx[hidx] = o;
    if (agg_out) *(float4*)&agg_out[hidx] = o;
}

__global__ void lstm_gate_kernel(const float* __restrict__ g1,
                                 const float* __restrict__ g2,
                                 float* __restrict__ hs, float* __restrict__ cs) {
    size_t idx = (size_t)blockIdx.x * blockDim.x + threadIdx.x;
    if (idx >= (size_t)N_GRAPHS * D) return;
    int b = (int)(idx >> 8);
    int d = (int)(idx & 255);
    size_t base = (size_t)b * 4 * D + d;
    float ig = sigmoidf_(g1[base] + g2[base]);
    float fg = sigmoidf_(g1[base + D] + g2[base + D]);
    float gg = tanhf(g1[base + 2 * D] + g2[base + 2 * D]);
    float og = sigmoidf_(g1[base + 3 * D] + g2[base + 3 * D]);
    float c = fg * cs[idx] + ig * gg;
    cs[idx] = c;
    hs[idx] = og * tanhf(c);
}

// ---------------- Set2Set attention ----------------
__global__ void s2s_prep_kernel(float* __restrict__ qstar,
                                const float* __restrict__ hs,
                                float* __restrict__ m, float* __restrict__ norm) {
    size_t i = (size_t)blockIdx.x * blockDim.x + threadIdx.x;
    if (i < N_GRAPHS) { m[i] = -INFINITY; norm[i] = 0.f; }
    if (i < (size_t)N_GRAPHS * D) {
        int b = (int)(i >> 8);
        int d = (int)(i & 255);
        qstar[(size_t)b * 2 * D + d] = hs[i];
        qstar[(size_t)b * 2 * D + D + d] = 0.f;
    }
}

__global__ void attn_prod_kernel(const float* __restrict__ hs,
                                 const float* __restrict__ x,
                                 const int* __restrict__ batch,
                                 float* __restrict__ prod) {
    int warp = (int)(((size_t)blockIdx.x * blockDim.x + threadIdx.x) >> 5);
    int lane = threadIdx.x & 31;
    if (warp >= N_NODES) return;
    int b = batch[warp];
    const float* q = hs + (size_t)b * D;
    const float* xv = x + (size_t)warp * D;
    float s = 0.f;
#pragma unroll
    for (int j = 0; j < D / 32; j++) s += q[lane + j * 32] * xv[lane + j * 32];
#pragma unroll
    for (int o = 16; o; o >>= 1) s += __shfl_xor_sync(0xFFFFFFFFu, s, o);
    if (lane == 0) prod[warp] = s;
}

__global__ void attn_max_kernel(const int* __restrict__ batch,
                                const float* __restrict__ prod,
                                float* __restrict__ m) {
    int n = (int)((size_t)blockIdx.x * blockDim.x + threadIdx.x);
    if (n >= N_NODES) return;
    atomicMaxFloat(&m[batch[n]], prod[n]);
}

__global__ void attn_expnorm_kernel(const int* __restrict__ batch,
                                    float* __restrict__ prod,
                                    const float* __restrict__ m,
                                    float* __restrict__ norm) {
    int n = (int)((size_t)blockIdx.x * blockDim.x + threadIdx.x);
    if (n >= N_NODES) return;
    int b = batch[n];
    float a = expf(prod[n] - m[b]);
    prod[n] = a;
    atomicAdd(&norm[b], a);
}

__global__ void attn_scatter_kernel(const int* __restrict__ batch,
                                    const float* __restrict__ prod,
                                    const float* __restrict__ norm,
                                    const float* __restrict__ x,
                                    float* __restrict__ qstar) {
    size_t idx = (size_t)blockIdx.x * blockDim.x + threadIdx.x;
    if (idx >= (size_t)N_NODES * 64) return;
    int n = (int)(idx >> 6);
    int c = (int)(idx & 63);
    int b = batch[n];
    float coef = prod[n] / (norm[b] + EPS);
    float4 xv = *(const float4*)&x[(size_t)n * D + c * 4];
    float4 v = make_float4(coef * xv.x, coef * xv.y, coef * xv.z, coef * xv.w);
    atomicAdd((float4*)&qstar[(size_t)b * 2 * D + D + c * 4], v);
}

__global__ void fc_kernel(const float* __restrict__ qstar,
                          const float* __restrict__ fw,
                          const float* __restrict__ fb,
                          float* __restrict__ out) {
    int warp = (int)(((size_t)blockIdx.x * blockDim.x + threadIdx.x) >> 5);
    int lane = threadIdx.x & 31;
    if (warp >= N_GRAPHS) return;
    float s = 0.f;
#pragma unroll
    for (int j = 0; j < (2 * D) / 32; j++)
        s += qstar[(size_t)warp * 2 * D + lane + j * 32] * fw[lane + j * 32];
#pragma unroll
    for (int o = 16; o; o >>= 1) s += __shfl_xor_sync(0xFFFFFFFFu, s, o);
    if (lane == 0) out[warp] = s + fb[0];
}

// ---------------- launch ----------------
extern "C" void kernel_launch(void* const* d_in, const int* in_sizes, int n_in,
                              void* d_out, int out_size) {
    const int* x_atoms = (const int*)d_in[0];
    const int* edge_index = (const int*)d_in[1];
    const int* edge_attr = (const int*)d_in[2];
    const int* batch = (const int*)d_in[3];
    const float* atom_emb = (const float*)d_in[4];
    const float* bond_emb = (const float*)d_in[5];
    const float* gin_w1 = (const float*)d_in[6];
    const float* gin_b1 = (const float*)d_in[7];
    const float* gin_w2 = (const float*)d_in[8];
    const float* gin_b2 = (const float*)d_in[9];
    const float* gru_wih = (const float*)d_in[10];
    const float* gru_whh = (const float*)d_in[11];
    const float* gru_bih = (const float*)d_in[12];
    const float* gru_bhh = (const float*)d_in[13];
    const float* lstm_wih = (const float*)d_in[14];
    const float* lstm_whh = (const float*)d_in[15];
    const float* lstm_bih = (const float*)d_in[16];
    const float* lstm_bhh = (const float*)d_in[17];
    const float* fc_w = (const float*)d_in[18];
    const float* fc_b = (const float*)d_in[19];
    float* out = (float*)d_out;

    float *hx0, *hx1, *e, *agg, *t, *xconv, *gi, *gh, *g1, *g2, *hs, *cs, *qstar,
        *prod, *mbuf, *norm, *w1t, *w2t;
    cudaGetSymbolAddress((void**)&hx0, g_hx0);
    cudaGetSymbolAddress((void**)&hx1, g_hx1);
    cudaGetSymbolAddress((void**)&e, g_e);
    cudaGetSymbolAddress((void**)&agg, g_agg);
    cudaGetSymbolAddress((void**)&t, g_t);
    cudaGetSymbolAddress((void**)&xconv, g_xconv);
    cudaGetSymbolAddress((void**)&gi, g_gi);
    cudaGetSymbolAddress((void**)&gh, g_gh);
    cudaGetSymbolAddress((void**)&g1, g_g1);
    cudaGetSymbolAddress((void**)&g2, g_g2);
    cudaGetSymbolAddress((void**)&hs, g_hs);
    cudaGetSymbolAddress((void**)&cs, g_cs);
    cudaGetSymbolAddress((void**)&qstar, g_qstar);
    cudaGetSymbolAddress((void**)&prod, g_prod);
    cudaGetSymbolAddress((void**)&mbuf, g_m);
    cudaGetSymbolAddress((void**)&norm, g_norm);
    cudaGetSymbolAddress((void**)&w1t, g_w1t);
    cudaGetSymbolAddress((void**)&w2t, g_w2t);

    cudaFuncSetAttribute(mma_gemm_kernel<false>,
                         cudaFuncAttributeMaxDynamicSharedMemorySize, GEMM_SMEM);
    cudaFuncSetAttribute(mma_gemm_kernel<true>,
                         cudaFuncAttributeMaxDynamicSharedMemorySize, GEMM_SMEM);

    const int TPB = 256;

    transpose_kernel<<<dim3(512 / 32, 256 / 32), dim3(32, 8)>>>(gin_w1, w1t, 256, 512);
    transpose_kernel<<<dim3(256 / 32, 512 / 32), dim3(32, 8)>>>(gin_w2, w2t, 512, 256);

    atom_encode_kernel<<<(N_NODES * 64) / TPB, TPB>>>(x_atoms, atom_emb, hx0, hx1, agg);
    bond_encode_kernel<<<(N_EDGES * 64) / TPB, TPB>>>(edge_attr, bond_emb, e);
    cudaMemsetAsync(hs, 0, (size_t)N_GRAPHS * D * sizeof(float));
    cudaMemsetAsync(cs, 0, (size_t)N_GRAPHS * D * sizeof(float));
    cudaMemsetAsync(qstar, 0, (size_t)N_GRAPHS * 2 * D * sizeof(float));

    for (int layer = 0; layer < 3; layer++) {
        // agg already holds x (from atom_encode / previous gate kernel)
        edge_scatter_kernel<<<(N_EDGES * 64) / TPB, TPB>>>(edge_index, hx1, e, agg);
        // GIN MLP (weights pre-transposed to [N,K])
        mma_gemm_kernel<true><<<dim3(512 / 256, N_NODES / 128), TPB, GEMM_SMEM>>>(
            agg, w1t, gin_b1, t, N_NODES, 512, 256);
        mma_gemm_kernel<false><<<dim3(256 / 256, N_NODES / 128), TPB, GEMM_SMEM>>>(
            t, w2t, gin_b2, xconv, N_NODES, 256, 512);
        // GRU layer 0
        mma_gemm_kernel<false><<<dim3(768 / 256, N_NODES / 128), TPB, GEMM_SMEM>>>(
            xconv, gru_wih, gru_bih, gi, N_NODES, 768, 256);
        mma_gemm_kernel<false><<<dim3(768 / 256, N_NODES / 128), TPB, GEMM_SMEM>>>(
            hx0, gru_whh, gru_bhh, gh, N_NODES, 768, 256);
        gru_gate_kernel<<<(N_NODES * 64) / TPB, TPB>>>(gi, gh, hx0, (float*)nullptr);
        // GRU layer 1
        mma_gemm_kernel<false><<<dim3(768 / 256, N_NODES / 128), TPB, GEMM_SMEM>>>(
            hx0, gru_wih + 768 * 256, gru_bih + 768, gi, N_NODES, 768, 256);
        mma_gemm_kernel<false><<<dim3(768 / 256, N_NODES / 128), TPB, GEMM_SMEM>>>(
            hx1, gru_whh + 768 * 256, gru_bhh + 768, gh, N_NODES, 768, 256);
        gru_gate_kernel<<<(N_NODES * 64) / TPB, TPB>>>(gi, gh, hx1,
                                                       layer < 2 ? agg : (float*)nullptr);
    }

    for (int step = 0; step < 3; step++) {
        mma_gemm_kernel<false><<<dim3(1024 / 256, N_GRAPHS / 128), TPB, GEMM_SMEM>>>(
            qstar, lstm_wih, lstm_bih, g1, N_GRAPHS, 1024, 512);
        mma_gemm_kernel<false><<<dim3(1024 / 256, N_GRAPHS / 128), TPB, GEMM_SMEM>>>(
            hs, lstm_whh, lstm_bhh, g2, N_GRAPHS, 1024, 256);
        lstm_gate_kernel<<<(N_GRAPHS * D) / TPB, TPB>>>(g1, g2, hs, cs);
        s2s_prep_kernel<<<(N_GRAPHS * D) / TPB, TPB>>>(qstar, hs, mbuf, norm);
        attn_prod_kernel<<<(N_NODES * 32) / TPB, TPB>>>(hs, hx1, batch, prod);
        attn_max_kernel<<<N_NODES / TPB, TPB>>>(batch, prod, mbuf);
        attn_expnorm_kernel<<<N_NODES / TPB, TPB>>>(batch, prod, mbuf, norm);
        attn_scatter_kernel<<<(N_NODES * 64) / TPB, TPB>>>(batch, prod, norm, hx1, qstar);
    }

    fc_kernel<<<(N_GRAPHS * 32) / TPB, TPB>>>(qstar, fc_w, fc_b, out);
}

// round 6
// speedup vs baseline: 2.7903x; 1.0180x over previous
#include <cuda_runtime.h>
#include <cuda_bf16.h>
#include <math.h>
#include <stdint.h>

#define N_NODES 131072
#define N_EDGES 524288
#define N_GRAPHS 4096
#define D 256
#define EPS 1e-10f

// ---------------- scratch (device globals; no allocation allowed) ----------
__device__ float g_hx0[N_NODES * D];
__device__ float g_hx1[N_NODES * D];          // aliases x
__device__ float g_e[N_EDGES * D];
__device__ float g_agg[N_NODES * D];
__device__ float g_t[N_NODES * 2 * D];
__device__ float g_xconv[N_NODES * D];
__device__ float g_gi[N_NODES * 3 * D];
__device__ float g_gh[N_NODES * 3 * D];
__device__ float g_g1[N_GRAPHS * 4 * D];
__device__ float g_g2[N_GRAPHS * 4 * D];
__device__ float g_hs[N_GRAPHS * D];
__device__ float g_cs[N_GRAPHS * D];
__device__ float g_qstar[N_GRAPHS * 2 * D];
__device__ float g_prod[N_NODES];
__device__ float g_m[N_GRAPHS];
__device__ float g_norm[N_GRAPHS];
__device__ float g_w1t[512 * 256];            // gin_w1^T  [N=512, K=256]
__device__ float g_w2t[256 * 512];            // gin_w2^T  [N=256, K=512]

// ---------------- helpers ----------------
__device__ __forceinline__ uint32_t smem_u32(const void* p) {
    uint32_t a;
    asm("{ .reg .u64 t; cvta.to.shared.u64 t, %1; cvt.u32.u64 %0, t; }" : "=r"(a) : "l"(p));
    return a;
}
__device__ __forceinline__ void atomicMaxFloat(float* addr, float val) {
    int* ia = (int*)addr;
    int cur = __float_as_int(*(volatile float*)addr);
    while (__int_as_float(cur) < val) {
        int old = atomicCAS(ia, cur, __float_as_int(val));
        if (old == cur) break;
        cur = old;
    }
}
__device__ __forceinline__ float sigmoidf_(float x) { return 1.0f / (1.0f + expf(-x)); }
__device__ __forceinline__ uint32_t to_tf32(float x) {
    uint32_t u;
    asm("cvt.rna.tf32.f32 %0, %1;" : "=r"(u) : "f"(x));
    return u;
}
__device__ __forceinline__ void mma_tf32(float* c, const uint32_t* a, const uint32_t* b) {
    asm volatile(
        "mma.sync.aligned.m16n8k8.row.col.f32.tf32.tf32.f32 "
        "{%0,%1,%2,%3}, {%4,%5,%6,%7}, {%8,%9}, {%0,%1,%2,%3};"
        : "+f"(c[0]), "+f"(c[1]), "+f"(c[2]), "+f"(c[3])
        : "r"(a[0]), "r"(a[1]), "r"(a[2]), "r"(a[3]), "r"(b[0]), "r"(b[1]));
}
__device__ __forceinline__ void ldsm_x4(uint32_t* r, uint32_t saddr) {
    asm volatile("ldmatrix.sync.aligned.m8n8.x4.shared.b16 {%0,%1,%2,%3}, [%4];"
                 : "=r"(r[0]), "=r"(r[1]), "=r"(r[2]), "=r"(r[3]) : "r"(saddr));
}

// ---------------- tf32 tensor-core GEMM: C[M,N] = A[M,K] @ B^T + bias ------
// A [M,K] row-major, B [N,K] row-major. M%128==0, N%256==0, K%32==0.
// Block 128x256, BK=32, 8 warps (2m x 4n), warp tile 64x64.
// LDG->reg prefetch, tf32 at STS, ldmatrix.x4 fragment loads,
// single __syncthreads per k-iter (STS targets the other buffer pre-mma).
static constexpr int GEMM_AST = 36;
static constexpr int GEMM_ASZ = 128 * GEMM_AST;       // words
static constexpr int GEMM_BSZ = 256 * GEMM_AST;
static constexpr int GEMM_BUF = GEMM_ASZ + GEMM_BSZ;  // 13824 words
static constexpr int GEMM_SMEM = 2 * GEMM_BUF * 4;    // 110592 B

template <bool RELU>
__global__ __launch_bounds__(256, 1) void mma_gemm_kernel(
    const float* __restrict__ A, const float* __restrict__ B,
    const float* __restrict__ bias, float* __restrict__ C,
    int M, int N, int K) {
    extern __shared__ uint32_t sm[];
    const int tid = threadIdx.x;
    const int lane = tid & 31;
    const int warp = tid >> 5;
    const int wm = warp & 1;          // 2 warps along M
    const int wn = warp >> 1;         // 4 warps along N
    const int m0 = blockIdx.y * 128;
    const int n0 = blockIdx.x * 256;
    const uint32_t sbase = smem_u32(sm);

    const int ar = tid >> 3, ac = tid & 7;   // staging coords

    // ldmatrix lane-local base offsets (bytes)
    const int g = lane >> 3, r8 = lane & 7;
    const uint32_t a_l = (uint32_t)(((wm * 64 + (g & 1) * 8 + r8) * GEMM_AST +
                                     (g >> 1) * 4) * 4);
    const uint32_t b_l = (uint32_t)(((wn * 64 + (g >> 1) * 8 + r8) * GEMM_AST +
                                     (g & 1) * 4) * 4) + GEMM_ASZ * 4;

    float acc[4][8][4];
#pragma unroll
    for (int i = 0; i < 4; i++)
#pragma unroll
        for (int j = 0; j < 8; j++)
#pragma unroll
            for (int q = 0; q < 4; q++) acc[i][j][q] = 0.f;

    const int niter = K >> 5;
    float4 pa[4], pb[8];

#define LDG_TILE(k0i)                                                              \
    do {                                                                           \
        const float* Ag = A + (size_t)m0 * K + (k0i) * 32;                         \
        const float* Bg = B + (size_t)n0 * K + (k0i) * 32;                         \
        _Pragma("unroll")                                                          \
        for (int i = 0; i < 4; i++)                                                \
            pa[i] = *(const float4*)&Ag[(size_t)(ar + i * 32) * K + ac * 4];       \
        _Pragma("unroll")                                                          \
        for (int i = 0; i < 8; i++)                                                \
            pb[i] = *(const float4*)&Bg[(size_t)(ar + i * 32) * K + ac * 4];       \
    } while (0)

#define STS_TILE(buf)                                                              \
    do {                                                                           \
        uint32_t* As_ = sm + (buf) * GEMM_BUF;                                     \
        uint32_t* Bs_ = As_ + GEMM_ASZ;                                            \
        _Pragma("unroll")                                                          \
        for (int i = 0; i < 4; i++) {                                              \
            uint32_t* p = &As_[(ar + i * 32) * GEMM_AST + ac * 4];                 \
            p[0] = to_tf32(pa[i].x); p[1] = to_tf32(pa[i].y);                      \
            p[2] = to_tf32(pa[i].z); p[3] = to_tf32(pa[i].w);                      \
        }                                                                          \
        _Pragma("unroll")                                                          \
        for (int i = 0; i < 8; i++) {                                              \
            uint32_t* p = &Bs_[(ar + i * 32) * GEMM_AST + ac * 4];                 \
            p[0] = to_tf32(pb[i].x); p[1] = to_tf32(pb[i].y);                      \
            p[2] = to_tf32(pb[i].z); p[3] = to_tf32(pb[i].w);                      \
        }                                                                          \
    } while (0)

    LDG_TILE(0);
    STS_TILE(0);
    __syncthreads();
    if (niter > 1) LDG_TILE(1);

    for (int k0i = 0; k0i < niter; k0i++) {
        // stage next buffer (other half; last reader synced a barrier ago)
        if (k0i + 1 < niter) STS_TILE((k0i + 1) & 1);
        if (k0i + 2 < niter) LDG_TILE(k0i + 2);

        const uint32_t base = sbase + (uint32_t)((k0i & 1) * GEMM_BUF * 4);
        const uint32_t aaddr = base + a_l;
        const uint32_t baddr = base + b_l;
#pragma unroll
        for (int ks = 0; ks < 4; ks++) {
            uint32_t a[4][4];
#pragma unroll
            for (int i = 0; i < 4; i++)
                ldsm_x4(a[i], aaddr + (uint32_t)(i * (16 * GEMM_AST * 4) + ks * 32));
            uint32_t b[8][2];
#pragma unroll
            for (int jj = 0; jj < 4; jj++) {
                uint32_t t[4];
                ldsm_x4(t, baddr + (uint32_t)(jj * (16 * GEMM_AST * 4) + ks * 32));
                b[2 * jj][0] = t[0]; b[2 * jj][1] = t[1];
                b[2 * jj + 1][0] = t[2]; b[2 * jj + 1][1] = t[3];
            }
#pragma unroll
            for (int i = 0; i < 4; i++)
#pragma unroll
                for (int j = 0; j < 8; j++) mma_tf32(acc[i][j], a[i], b[j]);
        }
        __syncthreads();
    }

    // epilogue
#pragma unroll
    for (int i = 0; i < 4; i++) {
        int mr = m0 + wm * 64 + i * 16 + (lane >> 2);
#pragma unroll
        for (int j = 0; j < 8; j++) {
            int nc = n0 + wn * 64 + j * 8 + (lane & 3) * 2;
            float b0 = bias[nc], b1 = bias[nc + 1];
            float v0 = acc[i][j][0] + b0;
            float v1 = acc[i][j][1] + b1;
            float v2 = acc[i][j][2] + b0;
            float v3 = acc[i][j][3] + b1;
            if (RELU) {
                v0 = fmaxf(v0, 0.f); v1 = fmaxf(v1, 0.f);
                v2 = fmaxf(v2, 0.f); v3 = fmaxf(v3, 0.f);
            }
            *(float2*)&C[(size_t)mr * N + nc] = make_float2(v0, v1);
            *(float2*)&C[(size_t)(mr + 8) * N + nc] = make_float2(v2, v3);
        }
    }
#undef LDG_TILE
#undef STS_TILE
}

// ---------------- weight transpose (tiny, once per launch) ----------------
__global__ void transpose_kernel(const float* __restrict__ in, float* __restrict__ out,
                                 int R, int C) {
    __shared__ float t[32][33];
    int c0 = blockIdx.x * 32, r0 = blockIdx.y * 32;
    for (int i = threadIdx.y; i < 32; i += 8)
        t[i][threadIdx.x] = in[(size_t)(r0 + i) * C + c0 + threadIdx.x];
    __syncthreads();
    for (int i = threadIdx.y; i < 32; i += 8)
        out[(size_t)(c0 + i) * R + r0 + threadIdx.x] = t[threadIdx.x][i];
}

// ---------------- encoders ----------------
__global__ void atom_encode_kernel(const int* __restrict__ xa,
                                   const float* __restrict__ emb,
                                   float* __restrict__ hx0, float* __restrict__ hx1,
                                   float* __restrict__ agg) {
    size_t idx = (size_t)blockIdx.x * blockDim.x + threadIdx.x;
    if (idx >= (size_t)N_NODES * 64) return;
    int n = (int)(idx >> 6);
    int c = (int)(idx & 63);
    float4 acc = make_float4(0.f, 0.f, 0.f, 0.f);
#pragma unroll
    for (int i = 0; i < 9; i++) {
        int t = xa[n * 9 + i];
        const float4 v = *(const float4*)&emb[((size_t)(i * 120 + t)) * D + c * 4];
        acc.x += v.x; acc.y += v.y; acc.z += v.z; acc.w += v.w;
    }
    *(float4*)&hx0[(size_t)n * D + c * 4] = acc;
    *(float4*)&hx1[(size_t)n * D + c * 4] = acc;
    *(float4*)&agg[(size_t)n * D + c * 4] = acc;
}

// bond table (3*6*256 floats = 18KB) cached in smem; grid-stride over edges
__global__ void bond_encode_kernel(const int* __restrict__ ea,
                                   const float* __restrict__ emb,
                                   float* __restrict__ e_out) {
    __shared__ float tab[3 * 6 * D];
    for (int i = threadIdx.x; i < 3 * 6 * D; i += blockDim.x) tab[i] = emb[i];
    __syncthreads();
    size_t total = (size_t)N_EDGES * 64;
    size_t stride = (size_t)gridDim.x * blockDim.x;
    for (size_t idx = (size_t)blockIdx.x * blockDim.x + threadIdx.x; idx < total;
         idx += stride) {
        int n = (int)(idx >> 6);
        int c = (int)(idx & 63);
        float4 acc = make_float4(0.f, 0.f, 0.f, 0.f);
#pragma unroll
        for (int i = 0; i < 3; i++) {
            int t = ea[n * 3 + i];
            const float4 v = *(const float4*)&tab[(i * 6 + t) * D + c * 4];
            acc.x += v.x; acc.y += v.y; acc.z += v.z; acc.w += v.w;
        }
        *(float4*)&e_out[(size_t)n * D + c * 4] = acc;
    }
}

// ---------------- edge scatter ----------------
__global__ void edge_scatter_kernel(const int* __restrict__ ei,
                                    const float* __restrict__ x,
                                    const float* __restrict__ e,
                                    float* __restrict__ agg) {
    size_t idx = (size_t)blockIdx.x * blockDim.x + threadIdx.x;
    if (idx >= (size_t)N_EDGES * 64) return;
    int ed = (int)(idx >> 6);
    int c = (int)(idx & 63);
    int s = ei[ed];
    int d = ei[N_EDGES + ed];
    float4 xv = *(const float4*)&x[(size_t)s * D + c * 4];
    float4 ev = *(const float4*)&e[(size_t)ed * D + c * 4];
    float4 m;
    m.x = fmaxf(xv.x + ev.x, 0.f);
    m.y = fmaxf(xv.y + ev.y, 0.f);
    m.z = fmaxf(xv.z + ev.z, 0.f);
    m.w = fmaxf(xv.w + ev.w, 0.f);
    atomicAdd((float4*)&agg[(size_t)d * D + c * 4], m);
}

// ---------------- GRU / LSTM gates ----------------
__global__ void gru_gate_kernel(const float* __restrict__ gi,
                                const float* __restrict__ gh,
                                float* __restrict__ hx,
                                float* __restrict__ agg_out) {
    size_t idx = (size_t)blockIdx.x * blockDim.x + threadIdx.x;
    if (idx >= (size_t)N_NODES * 64) return;
    int n = (int)(idx >> 6);
    int c = (int)(idx & 63);
    size_t base = (size_t)n * 3 * D + c * 4;
    float4 ir = *(const float4*)&gi[base];
    float4 iz = *(const float4*)&gi[base + D];
    float4 in_ = *(const float4*)&gi[base + 2 * D];
    float4 hr = *(const float4*)&gh[base];
    float4 hz = *(const float4*)&gh[base + D];
    float4 hn = *(const float4*)&gh[base + 2 * D];
    size_t hidx = (size_t)n * D + c * 4;
    float4 hp = *(const float4*)&hx[hidx];
    float4 o;
#define GRU1(X)                                                        \
    {                                                                  \
        float r = sigmoidf_(ir.X + hr.X);                              \
        float z = sigmoidf_(iz.X + hz.X);                              \
        float nn = tanhf(in_.X + r * hn.X);                            \
        o.X = (1.0f - z) * nn + z * hp.X;                              \
    }
    GRU1(x) GRU1(y) GRU1(z) GRU1(w)
#undef GRU1
    *(float4*)&hx[hidx] = o;
    if (agg_out) *(float4*)&agg_out[hidx] = o;
}

__global__ void lstm_gate_kernel(const float* __restrict__ g1,
                                 const float* __restrict__ g2,
                                 float* __restrict__ hs, float* __restrict__ cs) {
    size_t idx = (size_t)blockIdx.x * blockDim.x + threadIdx.x;
    if (idx >= (size_t)N_GRAPHS * D) return;
    int b = (int)(idx >> 8);
    int d = (int)(idx & 255);
    size_t base = (size_t)b * 4 * D + d;
    float ig = sigmoidf_(g1[base] + g2[base]);
    float fg = sigmoidf_(g1[base + D] + g2[base + D]);
    float gg = tanhf(g1[base + 2 * D] + g2[base + 2 * D]);
    float og = sigmoidf_(g1[base + 3 * D] + g2[base + 3 * D]);
    float c = fg * cs[idx] + ig * gg;
    cs[idx] = c;
    hs[idx] = og * tanhf(c);
}

// ---------------- Set2Set attention ----------------
__global__ void s2s_prep_kernel(float* __restrict__ qstar,
                                const float* __restrict__ hs,
                                float* __restrict__ m, float* __restrict__ norm) {
    size_t i = (size_t)blockIdx.x * blockDim.x + threadIdx.x;
    if (i < N_GRAPHS) { m[i] = -INFINITY; norm[i] = 0.f; }
    if (i < (size_t)N_GRAPHS * D) {
        int b = (int)(i >> 8);
        int d = (int)(i & 255);
        qstar[(size_t)b * 2 * D + d] = hs[i];
        qstar[(size_t)b * 2 * D + D + d] = 0.f;
    }
}

__global__ void attn_prod_kernel(const float* __restrict__ hs,
                                 const float* __restrict__ x,
                                 const int* __restrict__ batch,
                                 float* __restrict__ prod) {
    int warp = (int)(((size_t)blockIdx.x * blockDim.x + threadIdx.x) >> 5);
    int lane = threadIdx.x & 31;
    if (warp >= N_NODES) return;
    int b = batch[warp];
    const float* q = hs + (size_t)b * D;
    const float* xv = x + (size_t)warp * D;
    float s = 0.f;
#pragma unroll
    for (int j = 0; j < D / 32; j++) s += q[lane + j * 32] * xv[lane + j * 32];
#pragma unroll
    for (int o = 16; o; o >>= 1) s += __shfl_xor_sync(0xFFFFFFFFu, s, o);
    if (lane == 0) prod[warp] = s;
}

__global__ void attn_max_kernel(const int* __restrict__ batch,
                                const float* __restrict__ prod,
                                float* __restrict__ m) {
    int n = (int)((size_t)blockIdx.x * blockDim.x + threadIdx.x);
    if (n >= N_NODES) return;
    atomicMaxFloat(&m[batch[n]], prod[n]);
}

__global__ void attn_expnorm_kernel(const int* __restrict__ batch,
                                    float* __restrict__ prod,
                                    const float* __restrict__ m,
                                    float* __restrict__ norm) {
    int n = (int)((size_t)blockIdx.x * blockDim.x + threadIdx.x);
    if (n >= N_NODES) return;
    int b = batch[n];
    float a = expf(prod[n] - m[b]);
    prod[n] = a;
    atomicAdd(&norm[b], a);
}

__global__ void attn_scatter_kernel(const int* __restrict__ batch,
                                    const float* __restrict__ prod,
                                    const float* __restrict__ norm,
                                    const float* __restrict__ x,
                                    float* __restrict__ qstar) {
    size_t idx = (size_t)blockIdx.x * blockDim.x + threadIdx.x;
    if (idx >= (size_t)N_NODES * 64) return;
    int n = (int)(idx >> 6);
    int c = (int)(idx & 63);
    int b = batch[n];
    float coef = prod[n] / (norm[b] + EPS);
    float4 xv = *(const float4*)&x[(size_t)n * D + c * 4];
    float4 v = make_float4(coef * xv.x, coef * xv.y, coef * xv.z, coef * xv.w);
    atomicAdd((float4*)&qstar[(size_t)b * 2 * D + D + c * 4], v);
}

__global__ void fc_kernel(const float* __restrict__ qstar,
                          const float* __restrict__ fw,
                          const float* __restrict__ fb,
                          float* __restrict__ out) {
    int warp = (int)(((size_t)blockIdx.x * blockDim.x + threadIdx.x) >> 5);
    int lane = threadIdx.x & 31;
    if (warp >= N_GRAPHS) return;
    float s = 0.f;
#pragma unroll
    for (int j = 0; j < (2 * D) / 32; j++)
        s += qstar[(size_t)warp * 2 * D + lane + j * 32] * fw[lane + j * 32];
#pragma unroll
    for (int o = 16; o; o >>= 1) s += __shfl_xor_sync(0xFFFFFFFFu, s, o);
    if (lane == 0) out[warp] = s + fb[0];
}

// ---------------- launch ----------------
extern "C" void kernel_launch(void* const* d_in, const int* in_sizes, int n_in,
                              void* d_out, int out_size) {
    const int* x_atoms = (const int*)d_in[0];
    const int* edge_index = (const int*)d_in[1];
    const int* edge_attr = (const int*)d_in[2];
    const int* batch = (const int*)d_in[3];
    const float* atom_emb = (const float*)d_in[4];
    const float* bond_emb = (const float*)d_in[5];
    const float* gin_w1 = (const float*)d_in[6];
    const float* gin_b1 = (const float*)d_in[7];
    const float* gin_w2 = (const float*)d_in[8];
    const float* gin_b2 = (const float*)d_in[9];
    const float* gru_wih = (const float*)d_in[10];
    const float* gru_whh = (const float*)d_in[11];
    const float* gru_bih = (const float*)d_in[12];
    const float* gru_bhh = (const float*)d_in[13];
    const float* lstm_wih = (const float*)d_in[14];
    const float* lstm_whh = (const float*)d_in[15];
    const float* lstm_bih = (const float*)d_in[16];
    const float* lstm_bhh = (const float*)d_in[17];
    const float* fc_w = (const float*)d_in[18];
    const float* fc_b = (const float*)d_in[19];
    float* out = (float*)d_out;

    float *hx0, *hx1, *e, *agg, *t, *xconv, *gi, *gh, *g1, *g2, *hs, *cs, *qstar,
        *prod, *mbuf, *norm, *w1t, *w2t;
    cudaGetSymbolAddress((void**)&hx0, g_hx0);
    cudaGetSymbolAddress((void**)&hx1, g_hx1);
    cudaGetSymbolAddress((void**)&e, g_e);
    cudaGetSymbolAddress((void**)&agg, g_agg);
    cudaGetSymbolAddress((void**)&t, g_t);
    cudaGetSymbolAddress((void**)&xconv, g_xconv);
    cudaGetSymbolAddress((void**)&gi, g_gi);
    cudaGetSymbolAddress((void**)&gh, g_gh);
    cudaGetSymbolAddress((void**)&g1, g_g1);
    cudaGetSymbolAddress((void**)&g2, g_g2);
    cudaGetSymbolAddress((void**)&hs, g_hs);
    cudaGetSymbolAddress((void**)&cs, g_cs);
    cudaGetSymbolAddress((void**)&qstar, g_qstar);
    cudaGetSymbolAddress((void**)&prod, g_prod);
    cudaGetSymbolAddress((void**)&mbuf, g_m);
    cudaGetSymbolAddress((void**)&norm, g_norm);
    cudaGetSymbolAddress((void**)&w1t, g_w1t);
    cudaGetSymbolAddress((void**)&w2t, g_w2t);

    cudaFuncSetAttribute(mma_gemm_kernel<false>,
                         cudaFuncAttributeMaxDynamicSharedMemorySize, GEMM_SMEM);
    cudaFuncSetAttribute(mma_gemm_kernel<true>,
                         cudaFuncAttributeMaxDynamicSharedMemorySize, GEMM_SMEM);

    const int TPB = 256;

    transpose_kernel<<<dim3(512 / 32, 256 / 32), dim3(32, 8)>>>(gin_w1, w1t, 256, 512);
    transpose_kernel<<<dim3(256 / 32, 512 / 32), dim3(32, 8)>>>(gin_w2, w2t, 512, 256);

    atom_encode_kernel<<<(N_NODES * 64) / TPB, TPB>>>(x_atoms, atom_emb, hx0, hx1, agg);
    bond_encode_kernel<<<2048, TPB>>>(edge_attr, bond_emb, e);
    cudaMemsetAsync(hs, 0, (size_t)N_GRAPHS * D * sizeof(float));
    cudaMemsetAsync(cs, 0, (size_t)N_GRAPHS * D * sizeof(float));
    cudaMemsetAsync(qstar, 0, (size_t)N_GRAPHS * 2 * D * sizeof(float));

    for (int layer = 0; layer < 3; layer++) {
        // agg already holds x (from atom_encode / previous gate kernel)
        edge_scatter_kernel<<<(N_EDGES * 64) / TPB, TPB>>>(edge_index, hx1, e, agg);
        // GIN MLP (weights pre-transposed to [N,K])
        mma_gemm_kernel<true><<<dim3(512 / 256, N_NODES / 128), TPB, GEMM_SMEM>>>(
            agg, w1t, gin_b1, t, N_NODES, 512, 256);
        mma_gemm_kernel<false><<<dim3(256 / 256, N_NODES / 128), TPB, GEMM_SMEM>>>(
            t, w2t, gin_b2, xconv, N_NODES, 256, 512);
        // GRU layer 0
        mma_gemm_kernel<false><<<dim3(768 / 256, N_NODES / 128), TPB, GEMM_SMEM>>>(
            xconv, gru_wih, gru_bih, gi, N_NODES, 768, 256);
        mma_gemm_kernel<false><<<dim3(768 / 256, N_NODES / 128), TPB, GEMM_SMEM>>>(
            hx0, gru_whh, gru_bhh, gh, N_NODES, 768, 256);
        gru_gate_kernel<<<(N_NODES * 64) / TPB, TPB>>>(gi, gh, hx0, (float*)nullptr);
        // GRU layer 1
        mma_gemm_kernel<false><<<dim3(768 / 256, N_NODES / 128), TPB, GEMM_SMEM>>>(
            hx0, gru_wih + 768 * 256, gru_bih + 768, gi, N_NODES, 768, 256);
        mma_gemm_kernel<false><<<dim3(768 / 256, N_NODES / 128), TPB, GEMM_SMEM>>>(
            hx1, gru_whh + 768 * 256, gru_bhh + 768, gh, N_NODES, 768, 256);
        gru_gate_kernel<<<(N_NODES * 64) / TPB, TPB>>>(gi, gh, hx1,
                                                       layer < 2 ? agg : (float*)nullptr);
    }

    for (int step = 0; step < 3; step++) {
        mma_gemm_kernel<false><<<dim3(1024 / 256, N_GRAPHS / 128), TPB, GEMM_SMEM>>>(
            qstar, lstm_wih, lstm_bih, g1, N_GRAPHS, 1024, 512);
        mma_gemm_kernel<false><<<dim3(1024 / 256, N_GRAPHS / 128), TPB, GEMM_SMEM>>>(
            hs, lstm_whh, lstm_bhh, g2, N_GRAPHS, 1024, 256);
        lstm_gate_kernel<<<(N_GRAPHS * D) / TPB, TPB>>>(g1, g2, hs, cs);
        s2s_prep_kernel<<<(N_GRAPHS * D) / TPB, TPB>>>(qstar, hs, mbuf, norm);
        attn_prod_kernel<<<(N_NODES * 32) / TPB, TPB>>>(hs, hx1, batch, prod);
        attn_max_kernel<<<N_NODES / TPB, TPB>>>(batch, prod, mbuf);
        attn_expnorm_kernel<<<N_NODES / TPB, TPB>>>(batch, prod, mbuf, norm);
        attn_scatter_kernel<<<(N_NODES * 64) / TPB, TPB>>>(batch, prod, norm, hx1, qstar);
    }

    fc_kernel<<<(N_GRAPHS * 32) / TPB, TPB>>>(qstar, fc_w, fc_b, out);
}

// round 7
// speedup vs baseline: 3.4429x; 1.2339x over previous
#include <cuda_runtime.h>
#include <cuda_bf16.h>
#include <cuda_fp16.h>
#include <math.h>
#include <stdint.h>

#define N_NODES 131072
#define N_EDGES 524288
#define N_GRAPHS 4096
#define D 256
#define EPS 1e-10f

// ---------------- scratch (device globals; no allocation allowed) ----------
__device__ float g_hx0[N_NODES * D];
__device__ float g_hx1[N_NODES * D];          // aliases x
__device__ float g_e[N_EDGES * D];
__device__ float g_agg[N_NODES * D];
__device__ float g_t[N_NODES * 2 * D];
__device__ float g_xconv[N_NODES * D];
__device__ float g_gi[N_NODES * 3 * D];
__device__ float g_gh[N_NODES * 3 * D];
__device__ float g_g1[N_GRAPHS * 4 * D];
__device__ float g_g2[N_GRAPHS * 4 * D];
__device__ float g_hs[N_GRAPHS * D];
__device__ float g_cs[N_GRAPHS * D];
__device__ float g_qstar[N_GRAPHS * 2 * D];
__device__ float g_prod[N_NODES];
__device__ float g_m[N_GRAPHS];
__device__ float g_norm[N_GRAPHS];
__device__ float g_w1t[512 * 256];            // gin_w1^T  [N=512, K=256]
__device__ float g_w2t[256 * 512];            // gin_w2^T  [N=256, K=512]

// ---------------- helpers ----------------
__device__ __forceinline__ uint32_t smem_u32(const void* p) {
    uint32_t a;
    asm("{ .reg .u64 t; cvta.to.shared.u64 t, %1; cvt.u32.u64 %0, t; }" : "=r"(a) : "l"(p));
    return a;
}
__device__ __forceinline__ void atomicMaxFloat(float* addr, float val) {
    int* ia = (int*)addr;
    int cur = __float_as_int(*(volatile float*)addr);
    while (__int_as_float(cur) < val) {
        int old = atomicCAS(ia, cur, __float_as_int(val));
        if (old == cur) break;
        cur = old;
    }
}
__device__ __forceinline__ float sigmoidf_(float x) { return 1.0f / (1.0f + expf(-x)); }
__device__ __forceinline__ void mma_f16(float* c, const uint32_t* a, const uint32_t* b) {
    asm volatile(
        "mma.sync.aligned.m16n8k16.row.col.f32.f16.f16.f32 "
        "{%0,%1,%2,%3}, {%4,%5,%6,%7}, {%8,%9}, {%0,%1,%2,%3};"
        : "+f"(c[0]), "+f"(c[1]), "+f"(c[2]), "+f"(c[3])
        : "r"(a[0]), "r"(a[1]), "r"(a[2]), "r"(a[3]), "r"(b[0]), "r"(b[1]));
}
__device__ __forceinline__ void ldsm_x4(uint32_t* r, uint32_t saddr) {
    asm volatile("ldmatrix.sync.aligned.m8n8.x4.shared.b16 {%0,%1,%2,%3}, [%4];"
                 : "=r"(r[0]), "=r"(r[1]), "=r"(r[2]), "=r"(r[3]) : "r"(saddr));
}
__device__ __forceinline__ uint32_t pack_h2(float x, float y) {
    __half2 h = __float22half2_rn(make_float2(x, y));
    return *(uint32_t*)&h;
}

// ---------------- fp16 tensor-core GEMM: C[M,N] = A[M,K] @ B^T + bias ------
// A [M,K] row-major fp32, B [N,K] row-major fp32. M%128==0, N%256==0, K%32==0.
// Block 128x256, BK=32 (2 x k16 mma steps), 8 warps (2m x 4n), warp tile 64x64.
// fp32->fp16 (rn) at staging; fp32 accumulate. Row stride 40 halves (80B).
static constexpr int GEMM_RSTRIDE_B = 80;                   // bytes per smem row
static constexpr int GEMM_A_BYTES = 128 * GEMM_RSTRIDE_B;   // 10240
static constexpr int GEMM_B_BYTES = 256 * GEMM_RSTRIDE_B;   // 20480
static constexpr int GEMM_BUF_BYTES = GEMM_A_BYTES + GEMM_B_BYTES;  // 30720
static constexpr int GEMM_SMEM = 2 * GEMM_BUF_BYTES;        // 61440

template <bool RELU>
__global__ __launch_bounds__(256, 1) void mma_gemm_kernel(
    const float* __restrict__ A, const float* __restrict__ B,
    const float* __restrict__ bias, float* __restrict__ C,
    int M, int N, int K) {
    extern __shared__ char smc[];
    const int tid = threadIdx.x;
    const int lane = tid & 31;
    const int warp = tid >> 5;
    const int wm = warp & 1;          // 2 warps along M
    const int wn = warp >> 1;         // 4 warps along N
    const int m0 = blockIdx.y * 128;
    const int n0 = blockIdx.x * 256;
    const uint32_t sbase = smem_u32(smc);

    const int ar = tid >> 3, ac = tid & 7;   // staging coords

    // ldmatrix lane-local offsets (bytes): g0: r0-7@k0-7, g1: r8-15@k0-7,
    // g2: r0-7@k8-15, g3: r8-15@k8-15
    const int g = lane >> 3, r8 = lane & 7;
    const uint32_t a_l = (uint32_t)((wm * 64 + (g & 1) * 8 + r8) * GEMM_RSTRIDE_B +
                                    (g >> 1) * 16);
    const uint32_t b_l = (uint32_t)((wn * 64 + (g & 1) * 8 + r8) * GEMM_RSTRIDE_B +
                                    (g >> 1) * 16) + GEMM_A_BYTES;

    float acc[4][8][4];
#pragma unroll
    for (int i = 0; i < 4; i++)
#pragma unroll
        for (int j = 0; j < 8; j++)
#pragma unroll
            for (int q = 0; q < 4; q++) acc[i][j][q] = 0.f;

    const int niter = K >> 5;
    float4 pa[4], pb[8];

#define LDG_TILE(k0i)                                                              \
    do {                                                                           \
        const float* Ag = A + (size_t)m0 * K + (k0i) * 32;                         \
        const float* Bg = B + (size_t)n0 * K + (k0i) * 32;                         \
        _Pragma("unroll")                                                          \
        for (int i = 0; i < 4; i++)                                                \
            pa[i] = *(const float4*)&Ag[(size_t)(ar + i * 32) * K + ac * 4];       \
        _Pragma("unroll")                                                          \
        for (int i = 0; i < 8; i++)                                                \
            pb[i] = *(const float4*)&Bg[(size_t)(ar + i * 32) * K + ac * 4];       \
    } while (0)

#define STS_TILE(buf)                                                              \
    do {                                                                           \
        char* Ab_ = smc + (buf) * GEMM_BUF_BYTES;                                  \
        char* Bb_ = Ab_ + GEMM_A_BYTES;                                            \
        _Pragma("unroll")                                                          \
        for (int i = 0; i < 4; i++) {                                              \
            uint2* p = (uint2*)(Ab_ + (ar + i * 32) * GEMM_RSTRIDE_B + ac * 8);    \
            *p = make_uint2(pack_h2(pa[i].x, pa[i].y), pack_h2(pa[i].z, pa[i].w)); \
        }                                                                          \
        _Pragma("unroll")                                                          \
        for (int i = 0; i < 8; i++) {                                              \
            uint2* p = (uint2*)(Bb_ + (ar + i * 32) * GEMM_RSTRIDE_B + ac * 8);    \
            *p = make_uint2(pack_h2(pb[i].x, pb[i].y), pack_h2(pb[i].z, pb[i].w)); \
        }                                                                          \
    } while (0)

    LDG_TILE(0);
    STS_TILE(0);
    __syncthreads();
    if (niter > 1) LDG_TILE(1);

    for (int k0i = 0; k0i < niter; k0i++) {
        if (k0i + 1 < niter) STS_TILE((k0i + 1) & 1);
        if (k0i + 2 < niter) LDG_TILE(k0i + 2);

        const uint32_t base = sbase + (uint32_t)((k0i & 1) * GEMM_BUF_BYTES);
        const uint32_t aaddr = base + a_l;
        const uint32_t baddr = base + b_l;
#pragma unroll
        for (int ks = 0; ks < 2; ks++) {      // two k16 steps per 32-k tile
            uint32_t a[4][4];
#pragma unroll
            for (int i = 0; i < 4; i++)
                ldsm_x4(a[i], aaddr + (uint32_t)(i * 16 * GEMM_RSTRIDE_B + ks * 32));
            uint32_t b[8][2];
#pragma unroll
            for (int jj = 0; jj < 4; jj++) {
                uint32_t t[4];
                ldsm_x4(t, baddr + (uint32_t)(jj * 16 * GEMM_RSTRIDE_B + ks * 32));
                b[2 * jj][0] = t[0]; b[2 * jj][1] = t[2];
                b[2 * jj + 1][0] = t[1]; b[2 * jj + 1][1] = t[3];
            }
#pragma unroll
            for (int i = 0; i < 4; i++)
#pragma unroll
                for (int j = 0; j < 8; j++) mma_f16(acc[i][j], a[i], b[j]);
        }
        __syncthreads();
    }

    // epilogue (C fragment layout identical to k8 variant)
#pragma unroll
    for (int i = 0; i < 4; i++) {
        int mr = m0 + wm * 64 + i * 16 + (lane >> 2);
#pragma unroll
        for (int j = 0; j < 8; j++) {
            int nc = n0 + wn * 64 + j * 8 + (lane & 3) * 2;
            float b0 = bias[nc], b1 = bias[nc + 1];
            float v0 = acc[i][j][0] + b0;
            float v1 = acc[i][j][1] + b1;
            float v2 = acc[i][j][2] + b0;
            float v3 = acc[i][j][3] + b1;
            if (RELU) {
                v0 = fmaxf(v0, 0.f); v1 = fmaxf(v1, 0.f);
                v2 = fmaxf(v2, 0.f); v3 = fmaxf(v3, 0.f);
            }
            *(float2*)&C[(size_t)mr * N + nc] = make_float2(v0, v1);
            *(float2*)&C[(size_t)(mr + 8) * N + nc] = make_float2(v2, v3);
        }
    }
#undef LDG_TILE
#undef STS_TILE
}

// ---------------- weight transpose (tiny, once per launch) ----------------
__global__ void transpose_kernel(const float* __restrict__ in, float* __restrict__ out,
                                 int R, int C) {
    __shared__ float t[32][33];
    int c0 = blockIdx.x * 32, r0 = blockIdx.y * 32;
    for (int i = threadIdx.y; i < 32; i += 8)
        t[i][threadIdx.x] = in[(size_t)(r0 + i) * C + c0 + threadIdx.x];
    __syncthreads();
    for (int i = threadIdx.y; i < 32; i += 8)
        out[(size_t)(c0 + i) * R + r0 + threadIdx.x] = t[threadIdx.x][i];
}

// ---------------- encoders ----------------
__global__ void atom_encode_kernel(const int* __restrict__ xa,
                                   const float* __restrict__ emb,
                                   float* __restrict__ hx0, float* __restrict__ hx1,
                                   float* __restrict__ agg) {
    size_t idx = (size_t)blockIdx.x * blockDim.x + threadIdx.x;
    if (idx >= (size_t)N_NODES * 64) return;
    int n = (int)(idx >> 6);
    int c = (int)(idx & 63);
    float4 acc = make_float4(0.f, 0.f, 0.f, 0.f);
#pragma unroll
    for (int i = 0; i < 9; i++) {
        int t = xa[n * 9 + i];
        const float4 v = *(const float4*)&emb[((size_t)(i * 120 + t)) * D + c * 4];
        acc.x += v.x; acc.y += v.y; acc.z += v.z; acc.w += v.w;
    }
    *(float4*)&hx0[(size_t)n * D + c * 4] = acc;
    *(float4*)&hx1[(size_t)n * D + c * 4] = acc;
    *(float4*)&agg[(size_t)n * D + c * 4] = acc;
}

// bond table (18KB) cached in smem; grid-stride over edges
__global__ void bond_encode_kernel(const int* __restrict__ ea,
                                   const float* __restrict__ emb,
                                   float* __restrict__ e_out) {
    __shared__ float tab[3 * 6 * D];
    for (int i = threadIdx.x; i < 3 * 6 * D; i += blockDim.x) tab[i] = emb[i];
    __syncthreads();
    size_t total = (size_t)N_EDGES * 64;
    size_t stride = (size_t)gridDim.x * blockDim.x;
    for (size_t idx = (size_t)blockIdx.x * blockDim.x + threadIdx.x; idx < total;
         idx += stride) {
        int n = (int)(idx >> 6);
        int c = (int)(idx & 63);
        float4 acc = make_float4(0.f, 0.f, 0.f, 0.f);
#pragma unroll
        for (int i = 0; i < 3; i++) {
            int t = ea[n * 3 + i];
            const float4 v = *(const float4*)&tab[(i * 6 + t) * D + c * 4];
            acc.x += v.x; acc.y += v.y; acc.z += v.z; acc.w += v.w;
        }
        *(float4*)&e_out[(size_t)n * D + c * 4] = acc;
    }
}

// ---------------- edge scatter ----------------
__global__ void edge_scatter_kernel(const int* __restrict__ ei,
                                    const float* __restrict__ x,
                                    const float* __restrict__ e,
                                    float* __restrict__ agg) {
    size_t idx = (size_t)blockIdx.x * blockDim.x + threadIdx.x;
    if (idx >= (size_t)N_EDGES * 64) return;
    int ed = (int)(idx >> 6);
    int c = (int)(idx & 63);
    int s = ei[ed];
    int d = ei[N_EDGES + ed];
    float4 xv = *(const float4*)&x[(size_t)s * D + c * 4];
    float4 ev = *(const float4*)&e[(size_t)ed * D + c * 4];
    float4 m;
    m.x = fmaxf(xv.x + ev.x, 0.f);
    m.y = fmaxf(xv.y + ev.y, 0.f);
    m.z = fmaxf(xv.z + ev.z, 0.f);
    m.w = fmaxf(xv.w + ev.w, 0.f);
    atomicAdd((float4*)&agg[(size_t)d * D + c * 4], m);
}

// ---------------- GRU / LSTM gates ----------------
__global__ void gru_gate_kernel(const float* __restrict__ gi,
                                const float* __restrict__ gh,
                                float* __restrict__ hx,
                                float* __restrict__ agg_out) {
    size_t idx = (size_t)blockIdx.x * blockDim.x + threadIdx.x;
    if (idx >= (size_t)N_NODES * 64) return;
    int n = (int)(idx >> 6);
    int c = (int)(idx & 63);
    size_t base = (size_t)n * 3 * D + c * 4;
    float4 ir = *(const float4*)&gi[base];
    float4 iz = *(const float4*)&gi[base + D];
    float4 in_ = *(const float4*)&gi[base + 2 * D];
    float4 hr = *(const float4*)&gh[base];
    float4 hz = *(const float4*)&gh[base + D];
    float4 hn = *(const float4*)&gh[base + 2 * D];
    size_t hidx = (size_t)n * D + c * 4;
    float4 hp = *(const float4*)&hx[hidx];
    float4 o;
#define GRU1(X)                                                        \
    {                                                                  \
        float r = sigmoidf_(ir.X + hr.X);                              \
        float z = sigmoidf_(iz.X + hz.X);                              \
        float nn = tanhf(in_.X + r * hn.X);                            \
        o.X = (1.0f - z) * nn + z * hp.X;                              \
    }
    GRU1(x) GRU1(y) GRU1(z) GRU1(w)
#undef GRU1
    *(float4*)&hx[hidx] = o;
    if (agg_out) *(float4*)&agg_out[hidx] = o;
}

__global__ void lstm_gate_kernel(const float* __restrict__ g1,
                                 const float* __restrict__ g2,
                                 float* __restrict__ hs, float* __restrict__ cs) {
    size_t idx = (size_t)blockIdx.x * blockDim.x + threadIdx.x;
    if (idx >= (size_t)N_GRAPHS * D) return;
    int b = (int)(idx >> 8);
    int d = (int)(idx & 255);
    size_t base = (size_t)b * 4 * D + d;
    float ig = sigmoidf_(g1[base] + g2[base]);
    float fg = sigmoidf_(g1[base + D] + g2[base + D]);
    float gg = tanhf(g1[base + 2 * D] + g2[base + 2 * D]);
    float og = sigmoidf_(g1[base + 3 * D] + g2[base + 3 * D]);
    float c = fg * cs[idx] + ig * gg;
    cs[idx] = c;
    hs[idx] = og * tanhf(c);
}

// ---------------- Set2Set attention ----------------
__global__ void s2s_prep_kernel(float* __restrict__ qstar,
                                const float* __restrict__ hs,
                                float* __restrict__ m, float* __restrict__ norm) {
    size_t i = (size_t)blockIdx.x * blockDim.x + threadIdx.x;
    if (i < N_GRAPHS) { m[i] = -INFINITY; norm[i] = 0.f; }
    if (i < (size_t)N_GRAPHS * D) {
        int b = (int)(i >> 8);
        int d = (int)(i & 255);
        qstar[(size_t)b * 2 * D + d] = hs[i];
        qstar[(size_t)b * 2 * D + D + d] = 0.f;
    }
}

__global__ void attn_prod_kernel(const float* __restrict__ hs,
                                 const float* __restrict__ x,
                                 const int* __restrict__ batch,
                                 float* __restrict__ prod) {
    int warp = (int)(((size_t)blockIdx.x * blockDim.x + threadIdx.x) >> 5);
    int lane = threadIdx.x & 31;
    if (warp >= N_NODES) return;
    int b = batch[warp];
    const float* q = hs + (size_t)b * D;
    const float* xv = x + (size_t)warp * D;
    float s = 0.f;
#pragma unroll
    for (int j = 0; j < D / 32; j++) s += q[lane + j * 32] * xv[lane + j * 32];
#pragma unroll
    for (int o = 16; o; o >>= 1) s += __shfl_xor_sync(0xFFFFFFFFu, s, o);
    if (lane == 0) prod[warp] = s;
}

__global__ void attn_max_kernel(const int* __restrict__ batch,
                                const float* __restrict__ prod,
                                float* __restrict__ m) {
    int n = (int)((size_t)blockIdx.x * blockDim.x + threadIdx.x);
    if (n >= N_NODES) return;
    atomicMaxFloat(&m[batch[n]], prod[n]);
}

__global__ void attn_expnorm_kernel(const int* __restrict__ batch,
                                    float* __restrict__ prod,
                                    const float* __restrict__ m,
                                    float* __restrict__ norm) {
    int n = (int)((size_t)blockIdx.x * blockDim.x + threadIdx.x);
    if (n >= N_NODES) return;
    int b = batch[n];
    float a = expf(prod[n] - m[b]);
    prod[n] = a;
    atomicAdd(&norm[b], a);
}

__global__ void attn_scatter_kernel(const int* __restrict__ batch,
                                    const float* __restrict__ prod,
                                    const float* __restrict__ norm,
                                    const float* __restrict__ x,
                                    float* __restrict__ qstar) {
    size_t idx = (size_t)blockIdx.x * blockDim.x + threadIdx.x;
    if (idx >= (size_t)N_NODES * 64) return;
    int n = (int)(idx >> 6);
    int c = (int)(idx & 63);
    int b = batch[n];
    float coef = prod[n] / (norm[b] + EPS);
    float4 xv = *(const float4*)&x[(size_t)n * D + c * 4];
    float4 v = make_float4(coef * xv.x, coef * xv.y, coef * xv.z, coef * xv.w);
    atomicAdd((float4*)&qstar[(size_t)b * 2 * D + D + c * 4], v);
}

__global__ void fc_kernel(const float* __restrict__ qstar,
                          const float* __restrict__ fw,
                          const float* __restrict__ fb,
                          float* __restrict__ out) {
    int warp = (int)(((size_t)blockIdx.x * blockDim.x + threadIdx.x) >> 5);
    int lane = threadIdx.x & 31;
    if (warp >= N_GRAPHS) return;
    float s = 0.f;
#pragma unroll
    for (int j = 0; j < (2 * D) / 32; j++)
        s += qstar[(size_t)warp * 2 * D + lane + j * 32] * fw[lane + j * 32];
#pragma unroll
    for (int o = 16; o; o >>= 1) s += __shfl_xor_sync(0xFFFFFFFFu, s, o);
    if (lane == 0) out[warp] = s + fb[0];
}

// ---------------- launch ----------------
extern "C" void kernel_launch(void* const* d_in, const int* in_sizes, int n_in,
                              void* d_out, int out_size) {
    const int* x_atoms = (const int*)d_in[0];
    const int* edge_index = (const int*)d_in[1];
    const int* edge_attr = (const int*)d_in[2];
    const int* batch = (const int*)d_in[3];
    const float* atom_emb = (const float*)d_in[4];
    const float* bond_emb = (const float*)d_in[5];
    const float* gin_w1 = (const float*)d_in[6];
    const float* gin_b1 = (const float*)d_in[7];
    const float* gin_w2 = (const float*)d_in[8];
    const float* gin_b2 = (const float*)d_in[9];
    const float* gru_wih = (const float*)d_in[10];
    const float* gru_whh = (const float*)d_in[11];
    const float* gru_bih = (const float*)d_in[12];
    const float* gru_bhh = (const float*)d_in[13];
    const float* lstm_wih = (const float*)d_in[14];
    const float* lstm_whh = (const float*)d_in[15];
    const float* lstm_bih = (const float*)d_in[16];
    const float* lstm_bhh = (const float*)d_in[17];
    const float* fc_w = (const float*)d_in[18];
    const float* fc_b = (const float*)d_in[19];
    float* out = (float*)d_out;

    float *hx0, *hx1, *e, *agg, *t, *xconv, *gi, *gh, *g1, *g2, *hs, *cs, *qstar,
        *prod, *mbuf, *norm, *w1t, *w2t;
    cudaGetSymbolAddress((void**)&hx0, g_hx0);
    cudaGetSymbolAddress((void**)&hx1, g_hx1);
    cudaGetSymbolAddress((void**)&e, g_e);
    cudaGetSymbolAddress((void**)&agg, g_agg);
    cudaGetSymbolAddress((void**)&t, g_t);
    cudaGetSymbolAddress((void**)&xconv, g_xconv);
    cudaGetSymbolAddress((void**)&gi, g_gi);
    cudaGetSymbolAddress((void**)&gh, g_gh);
    cudaGetSymbolAddress((void**)&g1, g_g1);
    cudaGetSymbolAddress((void**)&g2, g_g2);
    cudaGetSymbolAddress((void**)&hs, g_hs);
    cudaGetSymbolAddress((void**)&cs, g_cs);
    cudaGetSymbolAddress((void**)&qstar, g_qstar);
    cudaGetSymbolAddress((void**)&prod, g_prod);
    cudaGetSymbolAddress((void**)&mbuf, g_m);
    cudaGetSymbolAddress((void**)&norm, g_norm);
    cudaGetSymbolAddress((void**)&w1t, g_w1t);
    cudaGetSymbolAddress((void**)&w2t, g_w2t);

    cudaFuncSetAttribute(mma_gemm_kernel<false>,
                         cudaFuncAttributeMaxDynamicSharedMemorySize, GEMM_SMEM);
    cudaFuncSetAttribute(mma_gemm_kernel<true>,
                         cudaFuncAttributeMaxDynamicSharedMemorySize, GEMM_SMEM);

    const int TPB = 256;

    transpose_kernel<<<dim3(512 / 32, 256 / 32), dim3(32, 8)>>>(gin_w1, w1t, 256, 512);
    transpose_kernel<<<dim3(256 / 32, 512 / 32), dim3(32, 8)>>>(gin_w2, w2t, 512, 256);

    atom_encode_kernel<<<(N_NODES * 64) / TPB, TPB>>>(x_atoms, atom_emb, hx0, hx1, agg);
    bond_encode_kernel<<<2048, TPB>>>(edge_attr, bond_emb, e);
    cudaMemsetAsync(hs, 0, (size_t)N_GRAPHS * D * sizeof(float));
    cudaMemsetAsync(cs, 0, (size_t)N_GRAPHS * D * sizeof(float));
    cudaMemsetAsync(qstar, 0, (size_t)N_GRAPHS * 2 * D * sizeof(float));

    for (int layer = 0; layer < 3; layer++) {
        edge_scatter_kernel<<<(N_EDGES * 64) / TPB, TPB>>>(edge_index, hx1, e, agg);
        // GIN MLP (weights pre-transposed to [N,K])
        mma_gemm_kernel<true><<<dim3(512 / 256, N_NODES / 128), TPB, GEMM_SMEM>>>(
            agg, w1t, gin_b1, t, N_NODES, 512, 256);
        mma_gemm_kernel<false><<<dim3(256 / 256, N_NODES / 128), TPB, GEMM_SMEM>>>(
            t, w2t, gin_b2, xconv, N_NODES, 256, 512);
        // GRU layer 0
        mma_gemm_kernel<false><<<dim3(768 / 256, N_NODES / 128), TPB, GEMM_SMEM>>>(
            xconv, gru_wih, gru_bih, gi, N_NODES, 768, 256);
        mma_gemm_kernel<false><<<dim3(768 / 256, N_NODES / 128), TPB, GEMM_SMEM>>>(
            hx0, gru_whh, gru_bhh, gh, N_NODES, 768, 256);
        gru_gate_kernel<<<(N_NODES * 64) / TPB, TPB>>>(gi, gh, hx0, (float*)nullptr);
        // GRU layer 1
        mma_gemm_kernel<false><<<dim3(768 / 256, N_NODES / 128), TPB, GEMM_SMEM>>>(
            hx0, gru_wih + 768 * 256, gru_bih + 768, gi, N_NODES, 768, 256);
        mma_gemm_kernel<false><<<dim3(768 / 256, N_NODES / 128), TPB, GEMM_SMEM>>>(
            hx1, gru_whh + 768 * 256, gru_bhh + 768, gh, N_NODES, 768, 256);
        gru_gate_kernel<<<(N_NODES * 64) / TPB, TPB>>>(gi, gh, hx1,
                                                       layer < 2 ? agg : (float*)nullptr);
    }

    for (int step = 0; step < 3; step++) {
        mma_gemm_kernel<false><<<dim3(1024 / 256, N_GRAPHS / 128), TPB, GEMM_SMEM>>>(
            qstar, lstm_wih, lstm_bih, g1, N_GRAPHS, 1024, 512);
        mma_gemm_kernel<false><<<dim3(1024 / 256, N_GRAPHS / 128), TPB, GEMM_SMEM>>>(
            hs, lstm_whh, lstm_bhh, g2, N_GRAPHS, 1024, 256);
        lstm_gate_kernel<<<(N_GRAPHS * D) / TPB, TPB>>>(g1, g2, hs, cs);
        s2s_prep_kernel<<<(N_GRAPHS * D) / TPB, TPB>>>(qstar, hs, mbuf, norm);
        attn_prod_kernel<<<(N_NODES * 32) / TPB, TPB>>>(hs, hx1, batch, prod);
        attn_max_kernel<<<N_NODES / TPB, TPB>>>(batch, prod, mbuf);
        attn_expnorm_kernel<<<N_NODES / TPB, TPB>>>(batch, prod, mbuf, norm);
        attn_scatter_kernel<<<(N_NODES * 64) / TPB, TPB>>>(batch, prod, norm, hx1, qstar);
    }

    fc_kernel<<<(N_GRAPHS * 32) / TPB, TPB>>>(qstar, fc_w, fc_b, out);
}

// round 8
// speedup vs baseline: 3.4435x; 1.0002x over previous
#include <cuda_runtime.h>
#include <cuda_bf16.h>
#include <cuda_fp16.h>
#include <math.h>
#include <stdint.h>

#define N_NODES 131072
#define N_EDGES 524288
#define N_GRAPHS 4096
#define D 256
#define EPS 1e-10f

// ---------------- scratch (device globals; no allocation allowed) ----------
__device__ float g_hx0[N_NODES * D];
__device__ float g_hx1[N_NODES * D];          // aliases x
__device__ float g_e[N_EDGES * D];
__device__ float g_agg[N_NODES * D];
__device__ float g_t[N_NODES * 2 * D];
__device__ float g_xconv[N_NODES * D];
__device__ float g_gi[N_NODES * 3 * D];
__device__ float g_gh[N_NODES * 3 * D];
__device__ float g_g1[N_GRAPHS * 4 * D];
__device__ float g_g2[N_GRAPHS * 4 * D];
__device__ float g_hs[N_GRAPHS * D];
__device__ float g_cs[N_GRAPHS * D];
__device__ float g_qstar[N_GRAPHS * 2 * D];
__device__ float g_prod[N_NODES];
__device__ float g_m[N_GRAPHS];
__device__ float g_norm[N_GRAPHS];
__device__ float g_w1t[512 * 256];            // gin_w1^T  [N=512, K=256]
__device__ float g_w2t[256 * 512];            // gin_w2^T  [N=256, K=512]

// ---------------- helpers ----------------
__device__ __forceinline__ uint32_t smem_u32(const void* p) {
    uint32_t a;
    asm("{ .reg .u64 t; cvta.to.shared.u64 t, %1; cvt.u32.u64 %0, t; }" : "=r"(a) : "l"(p));
    return a;
}
__device__ __forceinline__ void atomicMaxFloat(float* addr, float val) {
    int* ia = (int*)addr;
    int cur = __float_as_int(*(volatile float*)addr);
    while (__int_as_float(cur) < val) {
        int old = atomicCAS(ia, cur, __float_as_int(val));
        if (old == cur) break;
        cur = old;
    }
}
__device__ __forceinline__ float sigmoidf_(float x) { return 1.0f / (1.0f + expf(-x)); }
__device__ __forceinline__ void mma_f16(float* c, const uint32_t* a, const uint32_t* b) {
    asm volatile(
        "mma.sync.aligned.m16n8k16.row.col.f32.f16.f16.f32 "
        "{%0,%1,%2,%3}, {%4,%5,%6,%7}, {%8,%9}, {%0,%1,%2,%3};"
        : "+f"(c[0]), "+f"(c[1]), "+f"(c[2]), "+f"(c[3])
        : "r"(a[0]), "r"(a[1]), "r"(a[2]), "r"(a[3]), "r"(b[0]), "r"(b[1]));
}
__device__ __forceinline__ void ldsm_x4(uint32_t* r, uint32_t saddr) {
    asm volatile("ldmatrix.sync.aligned.m8n8.x4.shared.b16 {%0,%1,%2,%3}, [%4];"
                 : "=r"(r[0]), "=r"(r[1]), "=r"(r[2]), "=r"(r[3]) : "r"(saddr));
}
__device__ __forceinline__ uint32_t pack_h2(float x, float y) {
    __half2 h = __float22half2_rn(make_float2(x, y));
    return *(uint32_t*)&h;
}

// ---------------- fp16 tensor-core GEMM: C[M,N] = A[M,K] @ B^T + bias ------
// A [M,K] row-major fp32, B [N,K] row-major fp32. M%128==0, N%256==0, K%32==0.
// Block 128x256, BK=32 (2 x k16 mma), 16 warps (2m x 8n), warp tile 64x32.
// fp32->fp16 (rn) at staging; fp32 accumulate. Row stride 40 halves (80B).
static constexpr int GEMM_RSTRIDE_B = 80;                   // bytes per smem row
static constexpr int GEMM_A_BYTES = 128 * GEMM_RSTRIDE_B;   // 10240
static constexpr int GEMM_B_BYTES = 256 * GEMM_RSTRIDE_B;   // 20480
static constexpr int GEMM_BUF_BYTES = GEMM_A_BYTES + GEMM_B_BYTES;  // 30720
static constexpr int GEMM_SMEM = 2 * GEMM_BUF_BYTES;        // 61440
static constexpr int GEMM_TPB = 512;

template <bool RELU>
__global__ __launch_bounds__(GEMM_TPB, 1) void mma_gemm_kernel(
    const float* __restrict__ A, const float* __restrict__ B,
    const float* __restrict__ bias, float* __restrict__ C,
    int M, int N, int K) {
    extern __shared__ char smc[];
    const int tid = threadIdx.x;
    const int lane = tid & 31;
    const int warp = tid >> 5;
    const int wm = warp & 1;          // 2 warps along M
    const int wn = warp >> 1;         // 8 warps along N
    const int m0 = blockIdx.y * 128;
    const int n0 = blockIdx.x * 256;
    const uint32_t sbase = smem_u32(smc);

    const int ar = tid >> 3, ac = tid & 7;   // staging coords (64 rows/pass)

    const int g = lane >> 3, r8 = lane & 7;
    const uint32_t a_l = (uint32_t)((wm * 64 + (g & 1) * 8 + r8) * GEMM_RSTRIDE_B +
                                    (g >> 1) * 16);
    const uint32_t b_l = (uint32_t)((wn * 32 + (g & 1) * 8 + r8) * GEMM_RSTRIDE_B +
                                    (g >> 1) * 16) + GEMM_A_BYTES;

    float acc[4][4][4];
#pragma unroll
    for (int i = 0; i < 4; i++)
#pragma unroll
        for (int j = 0; j < 4; j++)
#pragma unroll
            for (int q = 0; q < 4; q++) acc[i][j][q] = 0.f;

    const int niter = K >> 5;
    float4 pa[2], pb[4];

#define LDG_TILE(k0i)                                                              \
    do {                                                                           \
        const float* Ag = A + (size_t)m0 * K + (k0i) * 32;                         \
        const float* Bg = B + (size_t)n0 * K + (k0i) * 32;                         \
        _Pragma("unroll")                                                          \
        for (int i = 0; i < 2; i++)                                                \
            pa[i] = *(const float4*)&Ag[(size_t)(ar + i * 64) * K + ac * 4];       \
        _Pragma("unroll")                                                          \
        for (int i = 0; i < 4; i++)                                                \
            pb[i] = *(const float4*)&Bg[(size_t)(ar + i * 64) * K + ac * 4];       \
    } while (0)

#define STS_TILE(buf)                                                              \
    do {                                                                           \
        char* Ab_ = smc + (buf) * GEMM_BUF_BYTES;                                  \
        char* Bb_ = Ab_ + GEMM_A_BYTES;                                            \
        _Pragma("unroll")                                                          \
        for (int i = 0; i < 2; i++) {                                              \
            uint2* p = (uint2*)(Ab_ + (ar + i * 64) * GEMM_RSTRIDE_B + ac * 8);    \
            *p = make_uint2(pack_h2(pa[i].x, pa[i].y), pack_h2(pa[i].z, pa[i].w)); \
        }                                                                          \
        _Pragma("unroll")                                                          \
        for (int i = 0; i < 4; i++) {                                              \
            uint2* p = (uint2*)(Bb_ + (ar + i * 64) * GEMM_RSTRIDE_B + ac * 8);    \
            *p = make_uint2(pack_h2(pb[i].x, pb[i].y), pack_h2(pb[i].z, pb[i].w)); \
        }                                                                          \
    } while (0)

    LDG_TILE(0);
    STS_TILE(0);
    __syncthreads();
    if (niter > 1) LDG_TILE(1);

    for (int k0i = 0; k0i < niter; k0i++) {
        if (k0i + 1 < niter) STS_TILE((k0i + 1) & 1);
        if (k0i + 2 < niter) LDG_TILE(k0i + 2);

        const uint32_t base = sbase + (uint32_t)((k0i & 1) * GEMM_BUF_BYTES);
        const uint32_t aaddr = base + a_l;
        const uint32_t baddr = base + b_l;
#pragma unroll
        for (int ks = 0; ks < 2; ks++) {      // two k16 steps per 32-k tile
            uint32_t a[4][4];
#pragma unroll
            for (int i = 0; i < 4; i++)
                ldsm_x4(a[i], aaddr + (uint32_t)(i * 16 * GEMM_RSTRIDE_B + ks * 32));
            uint32_t b[4][2];
#pragma unroll
            for (int jj = 0; jj < 2; jj++) {
                uint32_t t[4];
                ldsm_x4(t, baddr + (uint32_t)(jj * 16 * GEMM_RSTRIDE_B + ks * 32));
                b[2 * jj][0] = t[0]; b[2 * jj][1] = t[2];
                b[2 * jj + 1][0] = t[1]; b[2 * jj + 1][1] = t[3];
            }
#pragma unroll
            for (int i = 0; i < 4; i++)
#pragma unroll
                for (int j = 0; j < 4; j++) mma_f16(acc[i][j], a[i], b[j]);
        }
        __syncthreads();
    }

    // epilogue
#pragma unroll
    for (int i = 0; i < 4; i++) {
        int mr = m0 + wm * 64 + i * 16 + (lane >> 2);
#pragma unroll
        for (int j = 0; j < 4; j++) {
            int nc = n0 + wn * 32 + j * 8 + (lane & 3) * 2;
            float b0 = bias[nc], b1 = bias[nc + 1];
            float v0 = acc[i][j][0] + b0;
            float v1 = acc[i][j][1] + b1;
            float v2 = acc[i][j][2] + b0;
            float v3 = acc[i][j][3] + b1;
            if (RELU) {
                v0 = fmaxf(v0, 0.f); v1 = fmaxf(v1, 0.f);
                v2 = fmaxf(v2, 0.f); v3 = fmaxf(v3, 0.f);
            }
            *(float2*)&C[(size_t)mr * N + nc] = make_float2(v0, v1);
            *(float2*)&C[(size_t)(mr + 8) * N + nc] = make_float2(v2, v3);
        }
    }
#undef LDG_TILE
#undef STS_TILE
}

// ---------------- weight transpose (tiny, once per launch) ----------------
__global__ void transpose_kernel(const float* __restrict__ in, float* __restrict__ out,
                                 int R, int C) {
    __shared__ float t[32][33];
    int c0 = blockIdx.x * 32, r0 = blockIdx.y * 32;
    for (int i = threadIdx.y; i < 32; i += 8)
        t[i][threadIdx.x] = in[(size_t)(r0 + i) * C + c0 + threadIdx.x];
    __syncthreads();
    for (int i = threadIdx.y; i < 32; i += 8)
        out[(size_t)(c0 + i) * R + r0 + threadIdx.x] = t[threadIdx.x][i];
}

// ---------------- encoders ----------------
__global__ void atom_encode_kernel(const int* __restrict__ xa,
                                   const float* __restrict__ emb,
                                   float* __restrict__ hx0, float* __restrict__ hx1,
                                   float* __restrict__ agg) {
    size_t idx = (size_t)blockIdx.x * blockDim.x + threadIdx.x;
    if (idx >= (size_t)N_NODES * 64) return;
    int n = (int)(idx >> 6);
    int c = (int)(idx & 63);
    float4 acc = make_float4(0.f, 0.f, 0.f, 0.f);
#pragma unroll
    for (int i = 0; i < 9; i++) {
        int t = xa[n * 9 + i];
        const float4 v = *(const float4*)&emb[((size_t)(i * 120 + t)) * D + c * 4];
        acc.x += v.x; acc.y += v.y; acc.z += v.z; acc.w += v.w;
    }
    *(float4*)&hx0[(size_t)n * D + c * 4] = acc;
    *(float4*)&hx1[(size_t)n * D + c * 4] = acc;
    *(float4*)&agg[(size_t)n * D + c * 4] = acc;
}

// bond table (18KB) cached in smem; grid-stride over edges
__global__ void bond_encode_kernel(const int* __restrict__ ea,
                                   const float* __restrict__ emb,
                                   float* __restrict__ e_out) {
    __shared__ float tab[3 * 6 * D];
    for (int i = threadIdx.x; i < 3 * 6 * D; i += blockDim.x) tab[i] = emb[i];
    __syncthreads();
    size_t total = (size_t)N_EDGES * 64;
    size_t stride = (size_t)gridDim.x * blockDim.x;
    for (size_t idx = (size_t)blockIdx.x * blockDim.x + threadIdx.x; idx < total;
         idx += stride) {
        int n = (int)(idx >> 6);
        int c = (int)(idx & 63);
        float4 acc = make_float4(0.f, 0.f, 0.f, 0.f);
#pragma unroll
        for (int i = 0; i < 3; i++) {
            int t = ea[n * 3 + i];
            const float4 v = *(const float4*)&tab[(i * 6 + t) * D + c * 4];
            acc.x += v.x; acc.y += v.y; acc.z += v.z; acc.w += v.w;
        }
        *(float4*)&e_out[(size_t)n * D + c * 4] = acc;
    }
}

// ---------------- edge scatter ----------------
__global__ void edge_scatter_kernel(const int* __restrict__ ei,
                                    const float* __restrict__ x,
                                    const float* __restrict__ e,
                                    float* __restrict__ agg) {
    size_t idx = (size_t)blockIdx.x * blockDim.x + threadIdx.x;
    if (idx >= (size_t)N_EDGES * 64) return;
    int ed = (int)(idx >> 6);
    int c = (int)(idx & 63);
    int s = ei[ed];
    int d = ei[N_EDGES + ed];
    float4 xv = *(const float4*)&x[(size_t)s * D + c * 4];
    float4 ev = *(const float4*)&e[(size_t)ed * D + c * 4];
    float4 m;
    m.x = fmaxf(xv.x + ev.x, 0.f);
    m.y = fmaxf(xv.y + ev.y, 0.f);
    m.z = fmaxf(xv.z + ev.z, 0.f);
    m.w = fmaxf(xv.w + ev.w, 0.f);
    atomicAdd((float4*)&agg[(size_t)d * D + c * 4], m);
}

// ---------------- GRU / LSTM gates ----------------
__global__ void gru_gate_kernel(const float* __restrict__ gi,
                                const float* __restrict__ gh,
                                float* __restrict__ hx,
                                float* __restrict__ agg_out) {
    size_t idx = (size_t)blockIdx.x * blockDim.x + threadIdx.x;
    if (idx >= (size_t)N_NODES * 64) return;
    int n = (int)(idx >> 6);
    int c = (int)(idx & 63);
    size_t base = (size_t)n * 3 * D + c * 4;
    float4 ir = *(const float4*)&gi[base];
    float4 iz = *(const float4*)&gi[base + D];
    float4 in_ = *(const float4*)&gi[base + 2 * D];
    float4 hr = *(const float4*)&gh[base];
    float4 hz = *(const float4*)&gh[base + D];
    float4 hn = *(const float4*)&gh[base + 2 * D];
    size_t hidx = (size_t)n * D + c * 4;
    float4 hp = *(const float4*)&hx[hidx];
    float4 o;
#define GRU1(X)                                                        \
    {                                                                  \
        float r = sigmoidf_(ir.X + hr.X);                              \
        float z = sigmoidf_(iz.X + hz.X);                              \
        float nn = tanhf(in_.X + r * hn.X);                            \
        o.X = (1.0f - z) * nn + z * hp.X;                              \
    }
    GRU1(x) GRU1(y) GRU1(z) GRU1(w)
#undef GRU1
    *(float4*)&hx[hidx] = o;
    if (agg_out) *(float4*)&agg_out[hidx] = o;
}

__global__ void lstm_gate_kernel(const float* __restrict__ g1,
                                 const float* __restrict__ g2,
                                 float* __restrict__ hs, float* __restrict__ cs) {
    size_t idx = (size_t)blockIdx.x * blockDim.x + threadIdx.x;
    if (idx >= (size_t)N_GRAPHS * D) return;
    int b = (int)(idx >> 8);
    int d = (int)(idx & 255);
    size_t base = (size_t)b * 4 * D + d;
    float ig = sigmoidf_(g1[base] + g2[base]);
    float fg = sigmoidf_(g1[base + D] + g2[base + D]);
    float gg = tanhf(g1[base + 2 * D] + g2[base + 2 * D]);
    float og = sigmoidf_(g1[base + 3 * D] + g2[base + 3 * D]);
    float c = fg * cs[idx] + ig * gg;
    cs[idx] = c;
    hs[idx] = og * tanhf(c);
}

// ---------------- Set2Set attention ----------------
__global__ void s2s_prep_kernel(float* __restrict__ qstar,
                                const float* __restrict__ hs,
                                float* __restrict__ m, float* __restrict__ norm) {
    size_t i = (size_t)blockIdx.x * blockDim.x + threadIdx.x;
    if (i < N_GRAPHS) { m[i] = -INFINITY; norm[i] = 0.f; }
    if (i < (size_t)N_GRAPHS * D) {
        int b = (int)(i >> 8);
        int d = (int)(i & 255);
        qstar[(size_t)b * 2 * D + d] = hs[i];
        qstar[(size_t)b * 2 * D + D + d] = 0.f;
    }
}

__global__ void attn_prod_kernel(const float* __restrict__ hs,
                                 const float* __restrict__ x,
                                 const int* __restrict__ batch,
                                 float* __restrict__ prod) {
    int warp = (int)(((size_t)blockIdx.x * blockDim.x + threadIdx.x) >> 5);
    int lane = threadIdx.x & 31;
    if (warp >= N_NODES) return;
    int b = batch[warp];
    const float* q = hs + (size_t)b * D;
    const float* xv = x + (size_t)warp * D;
    float s = 0.f;
#pragma unroll
    for (int j = 0; j < D / 32; j++) s += q[lane + j * 32] * xv[lane + j * 32];
#pragma unroll
    for (int o = 16; o; o >>= 1) s += __shfl_xor_sync(0xFFFFFFFFu, s, o);
    if (lane == 0) prod[warp] = s;
}

__global__ void attn_max_kernel(const int* __restrict__ batch,
                                const float* __restrict__ prod,
                                float* __restrict__ m) {
    int n = (int)((size_t)blockIdx.x * blockDim.x + threadIdx.x);
    if (n >= N_NODES) return;
    atomicMaxFloat(&m[batch[n]], prod[n]);
}

__global__ void attn_expnorm_kernel(const int* __restrict__ batch,
                                    float* __restrict__ prod,
                                    const float* __restrict__ m,
                                    float* __restrict__ norm) {
    int n = (int)((size_t)blockIdx.x * blockDim.x + threadIdx.x);
    if (n >= N_NODES) return;
    int b = batch[n];
    float a = expf(prod[n] - m[b]);
    prod[n] = a;
    atomicAdd(&norm[b], a);
}

__global__ void attn_scatter_kernel(const int* __restrict__ batch,
                                    const float* __restrict__ prod,
                                    const float* __restrict__ norm,
                                    const float* __restrict__ x,
                                    float* __restrict__ qstar) {
    size_t idx = (size_t)blockIdx.x * blockDim.x + threadIdx.x;
    if (idx >= (size_t)N_NODES * 64) return;
    int n = (int)(idx >> 6);
    int c = (int)(idx & 63);
    int b = batch[n];
    float coef = prod[n] / (norm[b] + EPS);
    float4 xv = *(const float4*)&x[(size_t)n * D + c * 4];
    float4 v = make_float4(coef * xv.x, coef * xv.y, coef * xv.z, coef * xv.w);
    atomicAdd((float4*)&qstar[(size_t)b * 2 * D + D + c * 4], v);
}

__global__ void fc_kernel(const float* __restrict__ qstar,
                          const float* __restrict__ fw,
                          const float* __restrict__ fb,
                          float* __restrict__ out) {
    int warp = (int)(((size_t)blockIdx.x * blockDim.x + threadIdx.x) >> 5);
    int lane = threadIdx.x & 31;
    if (warp >= N_GRAPHS) return;
    float s = 0.f;
#pragma unroll
    for (int j = 0; j < (2 * D) / 32; j++)
        s += qstar[(size_t)warp * 2 * D + lane + j * 32] * fw[lane + j * 32];
#pragma unroll
    for (int o = 16; o; o >>= 1) s += __shfl_xor_sync(0xFFFFFFFFu, s, o);
    if (lane == 0) out[warp] = s + fb[0];
}

// ---------------- launch ----------------
extern "C" void kernel_launch(void* const* d_in, const int* in_sizes, int n_in,
                              void* d_out, int out_size) {
    const int* x_atoms = (const int*)d_in[0];
    const int* edge_index = (const int*)d_in[1];
    const int* edge_attr = (const int*)d_in[2];
    const int* batch = (const int*)d_in[3];
    const float* atom_emb = (const float*)d_in[4];
    const float* bond_emb = (const float*)d_in[5];
    const float* gin_w1 = (const float*)d_in[6];
    const float* gin_b1 = (const float*)d_in[7];
    const float* gin_w2 = (const float*)d_in[8];
    const float* gin_b2 = (const float*)d_in[9];
    const float* gru_wih = (const float*)d_in[10];
    const float* gru_whh = (const float*)d_in[11];
    const float* gru_bih = (const float*)d_in[12];
    const float* gru_bhh = (const float*)d_in[13];
    const float* lstm_wih = (const float*)d_in[14];
    const float* lstm_whh = (const float*)d_in[15];
    const float* lstm_bih = (const float*)d_in[16];
    const float* lstm_bhh = (const float*)d_in[17];
    const float* fc_w = (const float*)d_in[18];
    const float* fc_b = (const float*)d_in[19];
    float* out = (float*)d_out;

    float *hx0, *hx1, *e, *agg, *t, *xconv, *gi, *gh, *g1, *g2, *hs, *cs, *qstar,
        *prod, *mbuf, *norm, *w1t, *w2t;
    cudaGetSymbolAddress((void**)&hx0, g_hx0);
    cudaGetSymbolAddress((void**)&hx1, g_hx1);
    cudaGetSymbolAddress((void**)&e, g_e);
    cudaGetSymbolAddress((void**)&agg, g_agg);
    cudaGetSymbolAddress((void**)&t, g_t);
    cudaGetSymbolAddress((void**)&xconv, g_xconv);
    cudaGetSymbolAddress((void**)&gi, g_gi);
    cudaGetSymbolAddress((void**)&gh, g_gh);
    cudaGetSymbolAddress((void**)&g1, g_g1);
    cudaGetSymbolAddress((void**)&g2, g_g2);
    cudaGetSymbolAddress((void**)&hs, g_hs);
    cudaGetSymbolAddress((void**)&cs, g_cs);
    cudaGetSymbolAddress((void**)&qstar, g_qstar);
    cudaGetSymbolAddress((void**)&prod, g_prod);
    cudaGetSymbolAddress((void**)&mbuf, g_m);
    cudaGetSymbolAddress((void**)&norm, g_norm);
    cudaGetSymbolAddress((void**)&w1t, g_w1t);
    cudaGetSymbolAddress((void**)&w2t, g_w2t);

    cudaFuncSetAttribute(mma_gemm_kernel<false>,
                         cudaFuncAttributeMaxDynamicSharedMemorySize, GEMM_SMEM);
    cudaFuncSetAttribute(mma_gemm_kernel<true>,
                         cudaFuncAttributeMaxDynamicSharedMemorySize, GEMM_SMEM);

    const int TPB = 256;

    transpose_kernel<<<dim3(512 / 32, 256 / 32), dim3(32, 8)>>>(gin_w1, w1t, 256, 512);
    transpose_kernel<<<dim3(256 / 32, 512 / 32), dim3(32, 8)>>>(gin_w2, w2t, 512, 256);

    atom_encode_kernel<<<(N_NODES * 64) / TPB, TPB>>>(x_atoms, atom_emb, hx0, hx1, agg);
    bond_encode_kernel<<<2048, TPB>>>(edge_attr, bond_emb, e);
    cudaMemsetAsync(hs, 0, (size_t)N_GRAPHS * D * sizeof(float));
    cudaMemsetAsync(cs, 0, (size_t)N_GRAPHS * D * sizeof(float));
    cudaMemsetAsync(qstar, 0, (size_t)N_GRAPHS * 2 * D * sizeof(float));

    for (int layer = 0; layer < 3; layer++) {
        edge_scatter_kernel<<<(N_EDGES * 64) / TPB, TPB>>>(edge_index, hx1, e, agg);
        // GIN MLP (weights pre-transposed to [N,K])
        mma_gemm_kernel<true><<<dim3(512 / 256, N_NODES / 128), GEMM_TPB, GEMM_SMEM>>>(
            agg, w1t, gin_b1, t, N_NODES, 512, 256);
        mma_gemm_kernel<false><<<dim3(256 / 256, N_NODES / 128), GEMM_TPB, GEMM_SMEM>>>(
            t, w2t, gin_b2, xconv, N_NODES, 256, 512);
        // GRU layer 0
        mma_gemm_kernel<false><<<dim3(768 / 256, N_NODES / 128), GEMM_TPB, GEMM_SMEM>>>(
            xconv, gru_wih, gru_bih, gi, N_NODES, 768, 256);
        mma_gemm_kernel<false><<<dim3(768 / 256, N_NODES / 128), GEMM_TPB, GEMM_SMEM>>>(
            hx0, gru_whh, gru_bhh, gh, N_NODES, 768, 256);
        gru_gate_kernel<<<(N_NODES * 64) / TPB, TPB>>>(gi, gh, hx0, (float*)nullptr);
        // GRU layer 1
        mma_gemm_kernel<false><<<dim3(768 / 256, N_NODES / 128), GEMM_TPB, GEMM_SMEM>>>(
            hx0, gru_wih + 768 * 256, gru_bih + 768, gi, N_NODES, 768, 256);
        mma_gemm_kernel<false><<<dim3(768 / 256, N_NODES / 128), GEMM_TPB, GEMM_SMEM>>>(
            hx1, gru_whh + 768 * 256, gru_bhh + 768, gh, N_NODES, 768, 256);
        gru_gate_kernel<<<(N_NODES * 64) / TPB, TPB>>>(gi, gh, hx1,
                                                       layer < 2 ? agg : (float*)nullptr);
    }

    for (int step = 0; step < 3; step++) {
        mma_gemm_kernel<false><<<dim3(1024 / 256, N_GRAPHS / 128), GEMM_TPB, GEMM_SMEM>>>(
            qstar, lstm_wih, lstm_bih, g1, N_GRAPHS, 1024, 512);
        mma_gemm_kernel<false><<<dim3(1024 / 256, N_GRAPHS / 128), GEMM_TPB, GEMM_SMEM>>>(
            hs, lstm_whh, lstm_bhh, g2, N_GRAPHS, 1024, 256);
        lstm_gate_kernel<<<(N_GRAPHS * D) / TPB, TPB>>>(g1, g2, hs, cs);
        s2s_prep_kernel<<<(N_GRAPHS * D) / TPB, TPB>>>(qstar, hs, mbuf, norm);
        attn_prod_kernel<<<(N_NODES * 32) / TPB, TPB>>>(hs, hx1, batch, prod);
        attn_max_kernel<<<N_NODES / TPB, TPB>>>(batch, prod, mbuf);
        attn_expnorm_kernel<<<N_NODES / TPB, TPB>>>(batch, prod, mbuf, norm);
        attn_scatter_kernel<<<(N_NODES * 64) / TPB, TPB>>>(batch, prod, norm, hx1, qstar);
    }

    fc_kernel<<<(N_GRAPHS * 32) / TPB, TPB>>>(qstar, fc_w, fc_b, out);
}